// round 4
// baseline (speedup 1.0000x reference)
#include <cuda_runtime.h>
#include <cstdint>

typedef unsigned long long ull;

#define QL    2048
#define HISTL 2048
#define KLEN  4096
#define NH    12
#define NKVH  2
#define HD    128
#define HID   1536
#define GRP   6

// ---------------- scratch (static device globals; no allocation) ----------------
__device__ float g_q[QL * HID];          // Q projection, then RoPE'd in place: [t][h*128+d]
__device__ float g_kn[QL * NKVH * HD];   // new K projection (pre-RoPE)
__device__ float g_vn[QL * NKVH * HD];   // new V projection
__device__ float g_k[NKVH * KLEN * HD];  // full K: [kvh][pos][d]
__device__ float g_v[NKVH * KLEN * HD];  // full V
__device__ float g_attn[QL * HID];       // attention output pre-Wo

// ---------------- f32x2 packed helpers (Blackwell FFMA2) ----------------
__device__ __forceinline__ ull pack2(float lo, float hi) {
    ull r; asm("mov.b64 %0, {%1, %2};" : "=l"(r) : "f"(lo), "f"(hi)); return r;
}
__device__ __forceinline__ float2 unpack2(ull v) {
    float2 f; asm("mov.b64 {%0, %1}, %2;" : "=f"(f.x), "=f"(f.y) : "l"(v)); return f;
}
__device__ __forceinline__ ull fma2(ull a, ull b, ull c) {
    ull d; asm("fma.rn.f32x2 %0, %1, %2, %3;" : "=l"(d) : "l"(a), "l"(b), "l"(c)); return d;
}
__device__ __forceinline__ ull mul2(ull a, ull b) {
    ull d; asm("mul.rn.f32x2 %0, %1, %2;" : "=l"(d) : "l"(a), "l"(b)); return d;
}

// ---------------- 128x128x8 SGEMM tile (f32x2 inner product) ----------------
__device__ __forceinline__ void gemm_tile_128(
    const float* __restrict__ A, int lda,
    const float* __restrict__ B, int ldb,
    const float* __restrict__ bias,      // local col index, may be null
    float* __restrict__ C, int ldc,
    int m0, int K,
    ull* As2, float* Bs)
{
    const int tid = threadIdx.x;
    const int ty = tid >> 4, tx = tid & 15;

    ull acc[8][4];
#pragma unroll
    for (int i = 0; i < 8; i++)
#pragma unroll
        for (int c = 0; c < 4; c++) acc[i][c] = 0ull;

    const int ar = tid >> 1;             // tile row this thread loads (0..127)
    const int ak = (tid & 1) * 4;        // k sub-offset 0 or 4
    const float* Aptr = A + (ull)(m0 + ar) * lda + ak;
    const int bk = tid >> 5;             // 0..7
    const int bc = (tid & 31) * 4;       // 0..124
    const float* Bptr = B + (ull)bk * ldb + bc;

    for (int k0 = 0; k0 < K; k0 += 8) {
        float4 av = *(const float4*)(Aptr + k0);
        float4 bv = *(const float4*)(Bptr + (ull)k0 * ldb);
        __syncthreads();
        As2[(ak + 0) * 128 + ar] = pack2(av.x, av.x);
        As2[(ak + 1) * 128 + ar] = pack2(av.y, av.y);
        As2[(ak + 2) * 128 + ar] = pack2(av.z, av.z);
        As2[(ak + 3) * 128 + ar] = pack2(av.w, av.w);
        *(float4*)(Bs + bk * 128 + bc) = bv;
        __syncthreads();
#pragma unroll
        for (int kk = 0; kk < 8; kk++) {
            ull a2[8], b2[4];
            const ull* ap = As2 + kk * 128 + ty * 8;
#pragma unroll
            for (int i = 0; i < 8; i++) a2[i] = ap[i];
            const ull* bp = (const ull*)(Bs + kk * 128);
#pragma unroll
            for (int c = 0; c < 4; c++) b2[c] = bp[tx + c * 16];
#pragma unroll
            for (int i = 0; i < 8; i++)
#pragma unroll
                for (int c = 0; c < 4; c++) acc[i][c] = fma2(a2[i], b2[c], acc[i][c]);
        }
    }

#pragma unroll
    for (int i = 0; i < 8; i++) {
        const int row = m0 + ty * 8 + i;
        float* crow = C + (ull)row * ldc;
#pragma unroll
        for (int c = 0; c < 4; c++) {
            const int col = 2 * (tx + c * 16);
            float2 v = unpack2(acc[i][c]);
            if (bias) { v.x += bias[col]; v.y += bias[col + 1]; }
            crow[col] = v.x;
            crow[col + 1] = v.y;
        }
    }
}

// ---------------- fused QKV projection ----------------
__global__ __launch_bounds__(256, 2) void qkv_gemm_kernel(
    const float* __restrict__ x,
    const float* __restrict__ Wq, const float* __restrict__ bq,
    const float* __restrict__ Wk, const float* __restrict__ bk,
    const float* __restrict__ Wv, const float* __restrict__ bv)
{
    __shared__ ull As2[8 * 128];
    __shared__ float Bs[8 * 128];
    const int nb = blockIdx.x;
    const int m0 = blockIdx.y * 128;

    const float *B, *bias;
    float* C;
    int ldb, ldc;
    if (nb < 12)      { B = Wq + nb * 128;        bias = bq + nb * 128;        C = g_q  + nb * 128;        ldb = HID;       ldc = HID; }
    else if (nb < 14) { B = Wk + (nb - 12) * 128; bias = bk + (nb - 12) * 128; C = g_kn + (nb - 12) * 128; ldb = NKVH * HD; ldc = NKVH * HD; }
    else              { B = Wv + (nb - 14) * 128; bias = bv + (nb - 14) * 128; C = g_vn + (nb - 14) * 128; ldb = NKVH * HD; ldc = NKVH * HD; }

    gemm_tile_128(x, HID, B, ldb, bias, C, ldc, m0, HID, As2, Bs);
}

// ---------------- output projection ----------------
__global__ __launch_bounds__(256, 2) void out_gemm_kernel(
    const float* __restrict__ Wo, float* __restrict__ out)
{
    __shared__ ull As2[8 * 128];
    __shared__ float Bs[8 * 128];
    const int nb = blockIdx.x;      // 0..11
    const int m0 = blockIdx.y * 128;
    gemm_tile_128(g_attn, HID, Wo + nb * 128, HID, (const float*)0,
                  out + nb * 128, HID, m0, HID, As2, Bs);
}

// ---------------- RoPE on Q (in place) ----------------
__global__ void rope_q_kernel(const float* __restrict__ fcos, const float* __restrict__ fsin)
{
    const int t = blockIdx.x;
    const int h = threadIdx.x >> 6;     // 0..11
    const int i = threadIdx.x & 63;     // 0..63
    float* q = g_q + (ull)t * HID + h * HD;
    const float c = fcos[t * 64 + i];
    const float s = fsin[t * 64 + i];
    const float x1 = q[i];
    const float x2 = q[i + 64];
    q[i]      = x1 * c - x2 * s;
    q[i + 64] = x1 * s + x2 * c;
}

// ---------------- build full K/V ----------------
__global__ void build_kv_kernel(
    const float* __restrict__ k_hist, const float* __restrict__ v_hist,
    const float* __restrict__ fcos, const float* __restrict__ fsin)
{
    const int pos = blockIdx.x;
    const int kv = blockIdx.y;
    const int i = threadIdx.x;   // 0..63
    float* kd = g_k + ((ull)(kv * KLEN + pos)) * HD;
    float* vd = g_v + ((ull)(kv * KLEN + pos)) * HD;
    if (pos < HISTL) {
        const float* ks = k_hist + ((ull)pos * NKVH + kv) * HD;
        const float* vs = v_hist + ((ull)pos * NKVH + kv) * HD;
        kd[i] = ks[i]; kd[i + 64] = ks[i + 64];
        vd[i] = vs[i]; vd[i + 64] = vs[i + 64];
    } else {
        const int t = pos - HISTL;
        const float* ks = g_kn + (ull)t * (NKVH * HD) + kv * HD;
        const float* vs = g_vn + (ull)t * (NKVH * HD) + kv * HD;
        const float c = fcos[t * 64 + i];
        const float s = fsin[t * 64 + i];
        const float x1 = ks[i];
        const float x2 = ks[i + 64];
        kd[i]      = x1 * c - x2 * s;
        kd[i + 64] = x1 * s + x2 * c;
        vd[i] = vs[i]; vd[i + 64] = vs[i + 64];
    }
}

// ---------------- flash attention: 128q x 64k tiles ----------------
// 256 threads, per-thread micro-tile 8 rows x 4 key-cols (QK) / 4 d-pairs (PV).
// SMEM: Qs[128][130] Ks[64][130] Vs[64][130] Ps[128][65] = 166400 B (1 CTA/SM)
#define QT   128
#define KT   64
#define ASTR 130
#define PSTR 65
#define ATT_SMEM ((QT * ASTR + 2 * KT * ASTR + QT * PSTR) * 4)

__global__ __launch_bounds__(256, 1) void attention_kernel()
{
    extern __shared__ float sm[];
    float* Qs = sm;                      // 128 x 130
    float* Ks = Qs + QT * ASTR;          // 64 x 130
    float* Vs = Ks + KT * ASTR;          // 64 x 130
    float* Ps = Vs + KT * ASTR;          // 128 x 65

    const int h = blockIdx.x;
    const int qb = 15 - blockIdx.y;      // heavy blocks first
    const int kvh = h / GRP;
    const int tid = threadIdx.x;
    const int ty = tid >> 4, tx = tid & 15;
    const int q0 = qb * QT;

    // load Q tile (128 x 128)
#pragma unroll
    for (int it = 0; it < 16; it++) {
        const int idx = tid + it * 256;
        const int r = idx >> 5, c4 = (idx & 31) * 4;
        float4 v = *(const float4*)(g_q + (ull)(q0 + r) * HID + h * HD + c4);
        float* d = Qs + r * ASTR + c4;
        d[0] = v.x; d[1] = v.y; d[2] = v.z; d[3] = v.w;
    }

    float m[8], l[8];
    ull acc[8][4];
#pragma unroll
    for (int i = 0; i < 8; i++) {
        m[i] = -1e30f; l[i] = 0.f;
#pragma unroll
        for (int c = 0; c < 4; c++) acc[i][c] = 0ull;
    }

    const int n_tiles = 2 * qb + 34;
    const float* kbaseptr = g_k + (ull)kvh * KLEN * HD;
    const float* vbaseptr = g_v + (ull)kvh * KLEN * HD;

    for (int kt = 0; kt < n_tiles; kt++) {
        const int kb = kt * KT;
        __syncthreads();
        // load K,V tiles (64 x 128 each)
#pragma unroll
        for (int it = 0; it < 8; it++) {
            const int idx = tid + it * 256;
            const int r = idx >> 5, c4 = (idx & 31) * 4;
            float4 kv4 = *(const float4*)(kbaseptr + (ull)(kb + r) * HD + c4);
            float* kd = Ks + r * ASTR + c4;
            kd[0] = kv4.x; kd[1] = kv4.y; kd[2] = kv4.z; kd[3] = kv4.w;
            float4 vv4 = *(const float4*)(vbaseptr + (ull)(kb + r) * HD + c4);
            float* vdp = Vs + r * ASTR + c4;
            vdp[0] = vv4.x; vdp[1] = vv4.y; vdp[2] = vv4.z; vdp[3] = vv4.w;
        }
        __syncthreads();

        // S = Q K^T  (f32x2 packed over contraction dim)
        ull s2[8][4];
#pragma unroll
        for (int i = 0; i < 8; i++)
#pragma unroll
            for (int j = 0; j < 4; j++) s2[i][j] = 0ull;

        for (int kp = 0; kp < 64; kp++) {
            ull q2[8], k2[4];
            const ull* qp = (const ull*)(Qs + 2 * kp);
#pragma unroll
            for (int i = 0; i < 8; i++)
                q2[i] = *(const ull*)(Qs + (ty * 8 + i) * ASTR + 2 * kp);
#pragma unroll
            for (int j = 0; j < 4; j++)
                k2[j] = *(const ull*)(Ks + (tx + j * 16) * ASTR + 2 * kp);
#pragma unroll
            for (int i = 0; i < 8; i++)
#pragma unroll
                for (int j = 0; j < 4; j++) s2[i][j] = fma2(q2[i], k2[j], s2[i][j]);
            (void)qp;
        }

        const bool maskt = (kt >= 2 * qb + 32);
#pragma unroll
        for (int i = 0; i < 8; i++) {
            const int qg = q0 + ty * 8 + i;
            float sv[4];
#pragma unroll
            for (int j = 0; j < 4; j++) {
                float2 t2 = unpack2(s2[i][j]);
                float s = (t2.x + t2.y) * 0.08838834764831845f;
                if (maskt) {
                    const int kg = kb + tx + j * 16;
                    if (kg > qg + HISTL) s = -1e30f;
                }
                sv[j] = s;
            }
            float rmax = fmaxf(fmaxf(sv[0], sv[1]), fmaxf(sv[2], sv[3]));
#pragma unroll
            for (int off = 8; off >= 1; off >>= 1)
                rmax = fmaxf(rmax, __shfl_xor_sync(0xffffffffu, rmax, off, 16));
            const float mnew = fmaxf(m[i], rmax);
            const float corr = __expf(m[i] - mnew);
            float rsum = 0.f;
            float p[4];
#pragma unroll
            for (int j = 0; j < 4; j++) { p[j] = __expf(sv[j] - mnew); rsum += p[j]; }
#pragma unroll
            for (int off = 8; off >= 1; off >>= 1)
                rsum += __shfl_xor_sync(0xffffffffu, rsum, off, 16);
            l[i] = l[i] * corr + rsum;
            m[i] = mnew;
            const ull c2 = pack2(corr, corr);
#pragma unroll
            for (int c = 0; c < 4; c++) acc[i][c] = mul2(acc[i][c], c2);
#pragma unroll
            for (int j = 0; j < 4; j++)
                Ps[(ty * 8 + i) * PSTR + tx + j * 16] = p[j];
        }
        __syncthreads();

        // acc += P @ V  (f32x2 packed over output columns)
        for (int j = 0; j < KT; j++) {
            ull v2[4];
#pragma unroll
            for (int c = 0; c < 4; c++)
                v2[c] = *(const ull*)(Vs + j * ASTR + 2 * (tx + c * 16));
#pragma unroll
            for (int i = 0; i < 8; i++) {
                const float pv = Ps[(ty * 8 + i) * PSTR + j];
                const ull p2 = pack2(pv, pv);
#pragma unroll
                for (int c = 0; c < 4; c++) acc[i][c] = fma2(p2, v2[c], acc[i][c]);
            }
        }
    }

    // epilogue: normalize, write to g_attn [t][h*128+d]
#pragma unroll
    for (int i = 0; i < 8; i++) {
        const float inv = 1.f / l[i];
        const int row = q0 + ty * 8 + i;
        float* dst = g_attn + (ull)row * HID + h * HD;
#pragma unroll
        for (int c = 0; c < 4; c++) {
            float2 v = unpack2(acc[i][c]);
            const int col = 2 * (tx + c * 16);
            dst[col] = v.x * inv;
            dst[col + 1] = v.y * inv;
        }
    }
}

// ---------------- launch ----------------
extern "C" void kernel_launch(void* const* d_in, const int* in_sizes, int n_in,
                              void* d_out, int out_size)
{
    const float* x     = (const float*)d_in[0];
    const float* Wq    = (const float*)d_in[1];
    const float* bq    = (const float*)d_in[2];
    const float* Wk    = (const float*)d_in[3];
    const float* bk    = (const float*)d_in[4];
    const float* Wv    = (const float*)d_in[5];
    const float* bv    = (const float*)d_in[6];
    const float* Wo    = (const float*)d_in[7];
    const float* khist = (const float*)d_in[8];
    const float* vhist = (const float*)d_in[9];
    const float* fcos  = (const float*)d_in[10];
    const float* fsin  = (const float*)d_in[11];
    float* out = (float*)d_out;

    cudaFuncSetAttribute(attention_kernel,
                         cudaFuncAttributeMaxDynamicSharedMemorySize, ATT_SMEM);

    qkv_gemm_kernel<<<dim3(16, 16), 256>>>(x, Wq, bq, Wk, bk, Wv, bv);
    rope_q_kernel<<<QL, NH * 64>>>(fcos, fsin);
    build_kv_kernel<<<dim3(KLEN, NKVH), 64>>>(khist, vhist, fcos, fsin);
    attention_kernel<<<dim3(NH, 16), 256, ATT_SMEM>>>();
    out_gemm_kernel<<<dim3(12, 16), 256>>>(Wo, out);
}

// round 7
// speedup vs baseline: 2.0677x; 2.0677x over previous
#include <cuda_runtime.h>
#include <cuda_bf16.h>
#include <cstdint>

typedef unsigned long long ull;

#define QL    2048
#define HISTL 2048
#define KLEN  4096
#define NH    12
#define NKVH  2
#define HD    128
#define HID   1536
#define GRP   6
#define K3    4608           // 3 * 1536 (hi/lo compensated K extension)

// ---------------- scratch (static device globals; no allocation) ----------------
__device__ float g_q[QL * HID];          // Q projection, RoPE'd in place
__device__ float g_kn[QL * NKVH * HD];   // new K projection (pre-RoPE)
__device__ float g_vn[QL * NKVH * HD];   // new V projection
__device__ float g_k[NKVH * KLEN * HD];  // full K: [kvh][pos][d]
__device__ float g_v[NKVH * KLEN * HD];  // full V
__device__ float g_attn[QL * HID];       // attention output pre-Wo

// K-extended bf16 operands: A-side triplet (hi,hi,lo), B-side triplet (hi,lo,hi)
__device__ __nv_bfloat16 g_x3[QL * K3];        // x            [m][k3]
__device__ __nv_bfloat16 g_w3[2048 * K3];      // [Wq|Wk|Wv]^T [n][k3]
__device__ __nv_bfloat16 g_wo3[HID * K3];      // Wo^T         [n][k3]
__device__ __nv_bfloat16 g_at3[QL * K3];       // attn out     [m][k3]

// ---------------- f32x2 packed helpers (Blackwell FFMA2) ----------------
__device__ __forceinline__ ull pack2(float lo, float hi) {
    ull r; asm("mov.b64 %0, {%1, %2};" : "=l"(r) : "f"(lo), "f"(hi)); return r;
}
__device__ __forceinline__ float2 unpack2(ull v) {
    float2 f; asm("mov.b64 {%0, %1}, %2;" : "=f"(f.x), "=f"(f.y) : "l"(v)); return f;
}
__device__ __forceinline__ ull fma2(ull a, ull b, ull c) {
    ull d; asm("fma.rn.f32x2 %0, %1, %2, %3;" : "=l"(d) : "l"(a), "l"(b), "l"(c)); return d;
}
__device__ __forceinline__ ull mul2(ull a, ull b) {
    ull d; asm("mul.rn.f32x2 %0, %1, %2;" : "=l"(d) : "l"(a), "l"(b)); return d;
}

// ---------------- HMMA / ldmatrix / cp.async helpers (base sm_80+ features) ----------------
__device__ __forceinline__ uint32_t smem_u32(const void* p) {
    uint32_t a;
    asm("{ .reg .u64 t; cvta.to.shared.u64 t, %1; cvt.u32.u64 %0, t; }" : "=r"(a) : "l"(p));
    return a;
}
#define SWZ128(off) ((off) ^ (((off) >> 3) & 0x70))

__device__ __forceinline__ void ldsm4(uint32_t* r, uint32_t addr) {
    asm volatile("ldmatrix.sync.aligned.m8n8.x4.shared.b16 {%0,%1,%2,%3}, [%4];"
        : "=r"(r[0]), "=r"(r[1]), "=r"(r[2]), "=r"(r[3]) : "r"(addr));
}
__device__ __forceinline__ void mma16816(float* d, const uint32_t* a, const uint32_t* b) {
    asm volatile("mma.sync.aligned.m16n8k16.row.col.f32.bf16.bf16.f32 "
        "{%0,%1,%2,%3},{%4,%5,%6,%7},{%8,%9},{%0,%1,%2,%3};"
        : "+f"(d[0]), "+f"(d[1]), "+f"(d[2]), "+f"(d[3])
        : "r"(a[0]), "r"(a[1]), "r"(a[2]), "r"(a[3]), "r"(b[0]), "r"(b[1]));
}
__device__ __forceinline__ void cp_async16(uint32_t saddr, const void* gptr) {
    asm volatile("cp.async.cg.shared.global [%0], [%1], 16;"
        :: "r"(saddr), "l"((size_t)__cvta_generic_to_global(gptr)) : "memory");
}
__device__ __forceinline__ void cp_commit() {
    asm volatile("cp.async.commit_group;" ::: "memory");
}
__device__ __forceinline__ void cp_wait0() {
    asm volatile("cp.async.wait_group 0;" ::: "memory");
}

// ================= conversion kernels =================
__device__ __forceinline__ void split2(float v, __nv_bfloat16& h, __nv_bfloat16& l) {
    h = __float2bfloat16(v);
    l = __float2bfloat16(v - __bfloat162float(h));
}

// x -> g_x3  (A-side triplet h,h,l)
__global__ void conv_x3_kernel(const float* __restrict__ src) {
    const int i = blockIdx.x * blockDim.x + threadIdx.x;
    const int m = i / HID, k = i % HID;
    __nv_bfloat16 h, l;
    split2(src[i], h, l);
    __nv_bfloat16* p = g_x3 + (ull)m * K3 + 3 * k;
    p[0] = h; p[1] = h; p[2] = l;
}

// g_attn -> g_at3
__global__ void conv_a3_g_kernel() {
    const int i = blockIdx.x * blockDim.x + threadIdx.x;
    const int m = i / HID, k = i % HID;
    __nv_bfloat16 h, l;
    split2(g_attn[i], h, l);
    __nv_bfloat16* p = g_at3 + (ull)m * K3 + 3 * k;
    p[0] = h; p[1] = h; p[2] = l;
}

// transpose+split [k][n] -> [n][3k] (B-side triplet h,l,h). qkv: grid(64,48) block(32,8)
__global__ void conv_wqkv3_kernel(const float* __restrict__ Wq,
                                  const float* __restrict__ Wk,
                                  const float* __restrict__ Wv) {
    __shared__ float t[32][33];
    const int n0 = blockIdx.x * 32, k0 = blockIdx.y * 32;
    const int tx = threadIdx.x, ty = threadIdx.y;
    const float* W; int nb, ld;
    if (n0 < 1536)      { W = Wq; nb = n0;        ld = HID; }
    else if (n0 < 1792) { W = Wk; nb = n0 - 1536; ld = NKVH * HD; }
    else                { W = Wv; nb = n0 - 1792; ld = NKVH * HD; }
    for (int r = ty; r < 32; r += 8)
        t[r][tx] = W[(ull)(k0 + r) * ld + nb + tx];
    __syncthreads();
    for (int r = ty; r < 32; r += 8) {
        __nv_bfloat16 h, l;
        split2(t[tx][r], h, l);
        __nv_bfloat16* p = g_w3 + (ull)(n0 + r) * K3 + 3 * (k0 + tx);
        p[0] = h; p[1] = l; p[2] = h;
    }
}

// grid(48,48) block(32,8)
__global__ void conv_wo3_kernel(const float* __restrict__ Wo) {
    __shared__ float t[32][33];
    const int n0 = blockIdx.x * 32, k0 = blockIdx.y * 32;
    const int tx = threadIdx.x, ty = threadIdx.y;
    for (int r = ty; r < 32; r += 8)
        t[r][tx] = Wo[(ull)(k0 + r) * HID + n0 + tx];
    __syncthreads();
    for (int r = ty; r < 32; r += 8) {
        __nv_bfloat16 h, l;
        split2(t[tx][r], h, l);
        __nv_bfloat16* p = g_wo3 + (ull)(n0 + r) * K3 + 3 * (k0 + tx);
        p[0] = h; p[1] = l; p[2] = h;
    }
}

// ================= HMMA GEMM =================
// mode 0: C = g_x3 * g_w3^T (+biases, routed to g_q/g_kn/g_vn), grid.x = 16
// mode 1: C = g_at3 * g_wo3^T -> outp, grid.x = 12
// CTA tile 128x128, warp 64x32, K-chunk 64 bf16 (SW128), cp.async double buffer.
#define CHK     64
#define NCHUNK  (K3 / CHK)          // 72
#define TILE_B  16384               // 128 rows x 128 bytes
#define GEMM_SMEM (4 * TILE_B)      // A0,B0,A1,B1

__global__ __launch_bounds__(256, 2) void hmma_gemm_kernel(
    int mode, float* __restrict__ outp,
    const float* __restrict__ bq, const float* __restrict__ bk, const float* __restrict__ bv)
{
    extern __shared__ __align__(1024) char dynsm[];
    const uint32_t sbase = smem_u32(dynsm);
    const int tid  = threadIdx.x;
    const int lane = tid & 31;
    const int wid  = tid >> 5;
    const int wm   = wid >> 2;          // 0..1
    const int wn   = wid & 3;           // 0..3
    const int m0   = blockIdx.y * 128;
    const int n0   = blockIdx.x * 128;

    // device-side operand selection (device symbols referenced from device code)
    const __nv_bfloat16* __restrict__ A3 = (mode == 0) ? g_x3 : g_at3;
    const __nv_bfloat16* __restrict__ B3 = (mode == 0) ? g_w3 : g_wo3;

    float d[4][4][4];
#pragma unroll
    for (int mi = 0; mi < 4; mi++)
#pragma unroll
        for (int ni = 0; ni < 4; ni++)
#pragma unroll
            for (int r = 0; r < 4; r++) d[mi][ni][r] = 0.f;

    const int lr = tid >> 3;            // 0..31
    const int lg = tid & 7;             // 0..7 (16B units across 128B row)

    // prologue: chunk 0 -> buf 0
    {
        const uint32_t sA = sbase, sB = sbase + TILE_B;
#pragma unroll
        for (int it = 0; it < 4; it++) {
            const int r = lr + it * 32;
            const uint32_t so = SWZ128((uint32_t)(r * 128 + lg * 16));
            cp_async16(sA + so, A3 + (ull)(m0 + r) * K3 + lg * 8);
            cp_async16(sB + so, B3 + (ull)(n0 + r) * K3 + lg * 8);
        }
        cp_commit();
    }

    const int arow = wm * 64 + (lane & 15);
    const int acol = (lane & 16) ? 16 : 0;
    const int brow = wn * 32 + (lane & 7) + ((lane & 16) ? 8 : 0);
    const int bcol = (lane & 8) ? 16 : 0;

    for (int c = 0; c < NCHUNK; c++) {
        cp_wait0();
        __syncthreads();
        if (c + 1 < NCHUNK) {
            const uint32_t nb = ((c + 1) & 1) ? 2u * TILE_B : 0u;
            const uint32_t sA = sbase + nb, sB = sbase + nb + TILE_B;
            const int k0 = (c + 1) * CHK;
#pragma unroll
            for (int it = 0; it < 4; it++) {
                const int r = lr + it * 32;
                const uint32_t so = SWZ128((uint32_t)(r * 128 + lg * 16));
                cp_async16(sA + so, A3 + (ull)(m0 + r) * K3 + k0 + lg * 8);
                cp_async16(sB + so, B3 + (ull)(n0 + r) * K3 + k0 + lg * 8);
            }
            cp_commit();
        }
        const uint32_t cb = (c & 1) ? 2u * TILE_B : 0u;
        const uint32_t sA = sbase + cb, sB = sbase + cb + TILE_B;
#pragma unroll
        for (int kk = 0; kk < 4; kk++) {
            uint32_t a[4][4], bb[4][2];
#pragma unroll
            for (int mi = 0; mi < 4; mi++)
                ldsm4(a[mi], sA + SWZ128((uint32_t)((arow + mi * 16) * 128 + kk * 32 + acol)));
            {
                uint32_t t4[4];
                ldsm4(t4, sB + SWZ128((uint32_t)(brow * 128 + kk * 32 + bcol)));
                bb[0][0] = t4[0]; bb[0][1] = t4[1]; bb[1][0] = t4[2]; bb[1][1] = t4[3];
                ldsm4(t4, sB + SWZ128((uint32_t)((brow + 16) * 128 + kk * 32 + bcol)));
                bb[2][0] = t4[0]; bb[2][1] = t4[1]; bb[3][0] = t4[2]; bb[3][1] = t4[3];
            }
#pragma unroll
            for (int mi = 0; mi < 4; mi++)
#pragma unroll
                for (int ni = 0; ni < 4; ni++)
                    mma16816(d[mi][ni], a[mi], bb[ni]);
        }
        __syncthreads();
    }

    // epilogue routing (device symbols referenced from device code)
    float* dst; int ldc; const float* bias; int coff;
    if (mode == 1)        { dst = outp; ldc = HID;       bias = nullptr;          coff = n0; }
    else if (n0 < 1536)   { dst = g_q;  ldc = HID;       bias = bq + n0;          coff = n0; }
    else if (n0 < 1792)   { dst = g_kn; ldc = NKVH * HD; bias = bk + (n0 - 1536); coff = n0 - 1536; }
    else                  { dst = g_vn; ldc = NKVH * HD; bias = bv + (n0 - 1792); coff = n0 - 1792; }

#pragma unroll
    for (int mi = 0; mi < 4; mi++) {
        const int r0 = m0 + wm * 64 + mi * 16 + (lane >> 2);
#pragma unroll
        for (int ni = 0; ni < 4; ni++) {
            const int cl = wn * 32 + ni * 8 + (lane & 3) * 2;   // block-local col
            float b0 = 0.f, b1 = 0.f;
            if (bias) { b0 = bias[cl]; b1 = bias[cl + 1]; }
            float2 v0 = { d[mi][ni][0] + b0, d[mi][ni][1] + b1 };
            float2 v1 = { d[mi][ni][2] + b0, d[mi][ni][3] + b1 };
            *(float2*)(dst + (ull)r0 * ldc + coff + cl)       = v0;
            *(float2*)(dst + (ull)(r0 + 8) * ldc + coff + cl) = v1;
        }
    }
}

// ---------------- RoPE on Q (in place) ----------------
__global__ void rope_q_kernel(const float* __restrict__ fcos, const float* __restrict__ fsin)
{
    const int t = blockIdx.x;
    const int h = threadIdx.x >> 6;
    const int i = threadIdx.x & 63;
    float* q = g_q + (ull)t * HID + h * HD;
    const float c = fcos[t * 64 + i];
    const float s = fsin[t * 64 + i];
    const float x1 = q[i];
    const float x2 = q[i + 64];
    q[i]      = x1 * c - x2 * s;
    q[i + 64] = x1 * s + x2 * c;
}

// ---------------- build full K/V ----------------
__global__ void build_kv_kernel(
    const float* __restrict__ k_hist, const float* __restrict__ v_hist,
    const float* __restrict__ fcos, const float* __restrict__ fsin)
{
    const int pos = blockIdx.x;
    const int kv = blockIdx.y;
    const int i = threadIdx.x;
    float* kd = g_k + ((ull)(kv * KLEN + pos)) * HD;
    float* vd = g_v + ((ull)(kv * KLEN + pos)) * HD;
    if (pos < HISTL) {
        const float* ks = k_hist + ((ull)pos * NKVH + kv) * HD;
        const float* vs = v_hist + ((ull)pos * NKVH + kv) * HD;
        kd[i] = ks[i]; kd[i + 64] = ks[i + 64];
        vd[i] = vs[i]; vd[i + 64] = vs[i + 64];
    } else {
        const int t = pos - HISTL;
        const float* ks = g_kn + (ull)t * (NKVH * HD) + kv * HD;
        const float* vs = g_vn + (ull)t * (NKVH * HD) + kv * HD;
        const float c = fcos[t * 64 + i];
        const float s = fsin[t * 64 + i];
        const float x1 = ks[i];
        const float x2 = ks[i + 64];
        kd[i]      = x1 * c - x2 * s;
        kd[i + 64] = x1 * s + x2 * c;
        vd[i] = vs[i]; vd[i + 64] = vs[i + 64];
    }
}

// ---------------- flash attention (proven R2 config: 64q x 64k) ----------------
#define ASTR 130
#define ATT_SMEM ((3 * 64 * ASTR + 64 * 65) * 4)

__global__ __launch_bounds__(256) void attention_kernel()
{
    extern __shared__ float sm[];
    float* Qs = sm;
    float* Ks = Qs + 64 * ASTR;
    float* Vs = Ks + 64 * ASTR;
    float* Ps = Vs + 64 * ASTR;

    const int h = blockIdx.x;
    const int qb = 31 - blockIdx.y;       // heavy blocks first
    const int kvh = h / GRP;
    const int tid = threadIdx.x;
    const int ty = tid >> 4, tx = tid & 15;
    const int q0 = qb * 64;

#pragma unroll
    for (int it = 0; it < 8; it++) {
        const int idx = tid + it * 256;
        const int r = idx >> 5, c4 = (idx & 31) * 4;
        float4 v = *(const float4*)(g_q + (ull)(q0 + r) * HID + h * HD + c4);
        float* d = Qs + r * ASTR + c4;
        d[0] = v.x; d[1] = v.y; d[2] = v.z; d[3] = v.w;
    }

    float m[4], l[4];
    ull acc[4][4];
#pragma unroll
    for (int i = 0; i < 4; i++) {
        m[i] = -1e30f; l[i] = 0.f;
#pragma unroll
        for (int c = 0; c < 4; c++) acc[i][c] = 0ull;
    }

    const int n_tiles = qb + 33;
    const float* kbaseptr = g_k + (ull)kvh * KLEN * HD;
    const float* vbaseptr = g_v + (ull)kvh * KLEN * HD;

    for (int kt = 0; kt < n_tiles; kt++) {
        const int kb = kt * 64;
        __syncthreads();
#pragma unroll
        for (int it = 0; it < 8; it++) {
            const int idx = tid + it * 256;
            const int r = idx >> 5, c4 = (idx & 31) * 4;
            float4 kv4 = *(const float4*)(kbaseptr + (ull)(kb + r) * HD + c4);
            float* kd = Ks + r * ASTR + c4;
            kd[0] = kv4.x; kd[1] = kv4.y; kd[2] = kv4.z; kd[3] = kv4.w;
            float4 vv4 = *(const float4*)(vbaseptr + (ull)(kb + r) * HD + c4);
            float* vdp = Vs + r * ASTR + c4;
            vdp[0] = vv4.x; vdp[1] = vv4.y; vdp[2] = vv4.z; vdp[3] = vv4.w;
        }
        __syncthreads();

        ull s2[4][4];
#pragma unroll
        for (int i = 0; i < 4; i++)
#pragma unroll
            for (int j = 0; j < 4; j++) s2[i][j] = 0ull;

#pragma unroll 2
        for (int kp = 0; kp < 64; kp++) {
            ull q2[4], k2[4];
#pragma unroll
            for (int i = 0; i < 4; i++)
                q2[i] = *(const ull*)(Qs + (ty * 4 + i) * ASTR + 2 * kp);
#pragma unroll
            for (int j = 0; j < 4; j++)
                k2[j] = *(const ull*)(Ks + (tx + j * 16) * ASTR + 2 * kp);
#pragma unroll
            for (int i = 0; i < 4; i++)
#pragma unroll
                for (int j = 0; j < 4; j++) s2[i][j] = fma2(q2[i], k2[j], s2[i][j]);
        }

        const bool maskt = (kt == qb + 32);
#pragma unroll
        for (int i = 0; i < 4; i++) {
            const int qg = q0 + ty * 4 + i;
            float sv[4];
#pragma unroll
            for (int j = 0; j < 4; j++) {
                float2 t2 = unpack2(s2[i][j]);
                float s = (t2.x + t2.y) * 0.08838834764831845f;
                if (maskt) {
                    const int kg = kb + tx + j * 16;
                    if (kg > qg + HISTL) s = -1e30f;
                }
                sv[j] = s;
            }
            float rmax = fmaxf(fmaxf(sv[0], sv[1]), fmaxf(sv[2], sv[3]));
#pragma unroll
            for (int off = 8; off >= 1; off >>= 1)
                rmax = fmaxf(rmax, __shfl_xor_sync(0xffffffffu, rmax, off, 16));
            const float mnew = fmaxf(m[i], rmax);
            const float corr = __expf(m[i] - mnew);
            float rsum = 0.f;
            float p[4];
#pragma unroll
            for (int j = 0; j < 4; j++) { p[j] = __expf(sv[j] - mnew); rsum += p[j]; }
#pragma unroll
            for (int off = 8; off >= 1; off >>= 1)
                rsum += __shfl_xor_sync(0xffffffffu, rsum, off, 16);
            l[i] = l[i] * corr + rsum;
            m[i] = mnew;
            const ull c2 = pack2(corr, corr);
#pragma unroll
            for (int c = 0; c < 4; c++) acc[i][c] = mul2(acc[i][c], c2);
#pragma unroll
            for (int j = 0; j < 4; j++)
                Ps[(ty * 4 + i) * 65 + tx + j * 16] = p[j];
        }
        __syncthreads();

#pragma unroll 2
        for (int j = 0; j < 64; j++) {
            ull v2[4];
#pragma unroll
            for (int c = 0; c < 4; c++)
                v2[c] = *(const ull*)(Vs + j * ASTR + 2 * (tx + c * 16));
#pragma unroll
            for (int i = 0; i < 4; i++) {
                const float pv = Ps[(ty * 4 + i) * 65 + j];
                const ull p2 = pack2(pv, pv);
#pragma unroll
                for (int c = 0; c < 4; c++) acc[i][c] = fma2(p2, v2[c], acc[i][c]);
            }
        }
    }

#pragma unroll
    for (int i = 0; i < 4; i++) {
        const float inv = 1.f / l[i];
        const int row = q0 + ty * 4 + i;
        float* dst = g_attn + (ull)row * HID + h * HD;
#pragma unroll
        for (int c = 0; c < 4; c++) {
            float2 v = unpack2(acc[i][c]);
            const int col = 2 * (tx + c * 16);
            dst[col] = v.x * inv;
            dst[col + 1] = v.y * inv;
        }
    }
}

// ---------------- launch ----------------
extern "C" void kernel_launch(void* const* d_in, const int* in_sizes, int n_in,
                              void* d_out, int out_size)
{
    const float* x     = (const float*)d_in[0];
    const float* Wq    = (const float*)d_in[1];
    const float* bq    = (const float*)d_in[2];
    const float* Wk    = (const float*)d_in[3];
    const float* bk    = (const float*)d_in[4];
    const float* Wv    = (const float*)d_in[5];
    const float* bv    = (const float*)d_in[6];
    const float* Wo    = (const float*)d_in[7];
    const float* khist = (const float*)d_in[8];
    const float* vhist = (const float*)d_in[9];
    const float* fcos  = (const float*)d_in[10];
    const float* fsin  = (const float*)d_in[11];
    float* out = (float*)d_out;

    cudaFuncSetAttribute(attention_kernel,
                         cudaFuncAttributeMaxDynamicSharedMemorySize, ATT_SMEM);
    cudaFuncSetAttribute(hmma_gemm_kernel,
                         cudaFuncAttributeMaxDynamicSharedMemorySize, GEMM_SMEM);

    // operand prep: K-extended bf16 hi/lo operands
    conv_x3_kernel<<<QL * HID / 256, 256>>>(x);
    conv_wqkv3_kernel<<<dim3(64, 48), dim3(32, 8)>>>(Wq, Wk, Wv);
    conv_wo3_kernel<<<dim3(48, 48), dim3(32, 8)>>>(Wo);

    // QKV projection on HMMA (N=2048 over [Wq|Wk|Wv])
    hmma_gemm_kernel<<<dim3(16, 16), 256, GEMM_SMEM>>>(0, nullptr, bq, bk, bv);

    rope_q_kernel<<<QL, NH * 64>>>(fcos, fsin);
    build_kv_kernel<<<dim3(KLEN, NKVH), 64>>>(khist, vhist, fcos, fsin);

    attention_kernel<<<dim3(NH, 32), 256, ATT_SMEM>>>();

    // O projection on HMMA (N=1536)
    conv_a3_g_kernel<<<QL * HID / 256, 256>>>();
    hmma_gemm_kernel<<<dim3(12, 16), 256, GEMM_SMEM>>>(1, out, nullptr, nullptr, nullptr);
}

// round 8
// speedup vs baseline: 3.6098x; 1.7458x over previous
#include <cuda_runtime.h>
#include <cuda_bf16.h>
#include <cstdint>

typedef unsigned long long ull;

#define QL    2048
#define HISTL 2048
#define KLEN  4096
#define NH    12
#define NKVH  2
#define HD    128
#define HID   1536
#define GRP   6
#define K3    4608           // 3 * 1536 (hi/lo compensated K extension)
#define D3    384            // 3 * 128
#define PK3   192            // 3 * 64

// ---------------- scratch (static device globals; no allocation) ----------------
__device__ float g_q[QL * HID];          // Q projection (pre-RoPE, f32)
__device__ float g_kn[QL * NKVH * HD];   // new K projection (pre-RoPE)
__device__ float g_vn[QL * NKVH * HD];   // new V projection
__device__ float g_v[NKVH * KLEN * HD];  // full V (f32, for transpose)

// bf16 triplet operands
__device__ __nv_bfloat16 g_x3[QL * K3];          // x triplets (A: h,h,l)
__device__ __nv_bfloat16 g_w3[2048 * K3];        // [Wq|Wk|Wv]^T triplets (B: h,l,h)
__device__ __nv_bfloat16 g_wo3[HID * K3];        // Wo^T triplets (B)
__device__ __nv_bfloat16 g_at3[QL * K3];         // attention out triplets (A)
__device__ __nv_bfloat16 g_q3[NH * QL * D3];     // RoPE'd Q triplets (A): [(h*2048+t)][384]
__device__ __nv_bfloat16 g_k3[NKVH * KLEN * D3]; // full K triplets (B): [(kv*4096+pos)][384]
__device__ __nv_bfloat16 g_vt3[NKVH * HD * (3 * KLEN)]; // V^T triplets (B): [(kv*128+d)][3*4096]

// ---------------- helpers ----------------
__device__ __forceinline__ uint32_t smem_u32(const void* p) {
    uint32_t a;
    asm("{ .reg .u64 t; cvta.to.shared.u64 t, %1; cvt.u32.u64 %0, t; }" : "=r"(a) : "l"(p));
    return a;
}
#define SWZ128(off) ((off) ^ (((off) >> 3) & 0x70))

__device__ __forceinline__ void ldsm4(uint32_t* r, uint32_t addr) {
    asm volatile("ldmatrix.sync.aligned.m8n8.x4.shared.b16 {%0,%1,%2,%3}, [%4];"
        : "=r"(r[0]), "=r"(r[1]), "=r"(r[2]), "=r"(r[3]) : "r"(addr));
}
__device__ __forceinline__ void mma16816(float* d, const uint32_t* a, const uint32_t* b) {
    asm volatile("mma.sync.aligned.m16n8k16.row.col.f32.bf16.bf16.f32 "
        "{%0,%1,%2,%3},{%4,%5,%6,%7},{%8,%9},{%0,%1,%2,%3};"
        : "+f"(d[0]), "+f"(d[1]), "+f"(d[2]), "+f"(d[3])
        : "r"(a[0]), "r"(a[1]), "r"(a[2]), "r"(a[3]), "r"(b[0]), "r"(b[1]));
}
__device__ __forceinline__ void cp_async16(uint32_t saddr, const void* gptr) {
    asm volatile("cp.async.cg.shared.global [%0], [%1], 16;"
        :: "r"(saddr), "l"((size_t)__cvta_generic_to_global(gptr)) : "memory");
}
__device__ __forceinline__ void cp_commit() { asm volatile("cp.async.commit_group;" ::: "memory"); }
__device__ __forceinline__ void cp_wait0()  { asm volatile("cp.async.wait_group 0;" ::: "memory"); }

__device__ __forceinline__ void split2(float v, __nv_bfloat16& h, __nv_bfloat16& l) {
    h = __float2bfloat16(v);
    l = __float2bfloat16(v - __bfloat162float(h));
}
__device__ __forceinline__ uint32_t bfpack(__nv_bfloat16 a, __nv_bfloat16 b) {
    return (uint32_t)__bfloat16_as_ushort(a) | ((uint32_t)__bfloat16_as_ushort(b) << 16);
}

// ================= conversion kernels =================
__global__ void conv_x3_kernel(const float* __restrict__ src) {
    const int i = blockIdx.x * blockDim.x + threadIdx.x;
    const int m = i / HID, k = i % HID;
    __nv_bfloat16 h, l;
    split2(src[i], h, l);
    __nv_bfloat16* p = g_x3 + (ull)m * K3 + 3 * k;
    p[0] = h; p[1] = h; p[2] = l;
}

__global__ void conv_wqkv3_kernel(const float* __restrict__ Wq,
                                  const float* __restrict__ Wk,
                                  const float* __restrict__ Wv) {
    __shared__ float t[32][33];
    const int n0 = blockIdx.x * 32, k0 = blockIdx.y * 32;
    const int tx = threadIdx.x, ty = threadIdx.y;
    const float* W; int nb, ld;
    if (n0 < 1536)      { W = Wq; nb = n0;        ld = HID; }
    else if (n0 < 1792) { W = Wk; nb = n0 - 1536; ld = NKVH * HD; }
    else                { W = Wv; nb = n0 - 1792; ld = NKVH * HD; }
    for (int r = ty; r < 32; r += 8)
        t[r][tx] = W[(ull)(k0 + r) * ld + nb + tx];
    __syncthreads();
    for (int r = ty; r < 32; r += 8) {
        __nv_bfloat16 h, l;
        split2(t[tx][r], h, l);
        __nv_bfloat16* p = g_w3 + (ull)(n0 + r) * K3 + 3 * (k0 + tx);
        p[0] = h; p[1] = l; p[2] = h;
    }
}

__global__ void conv_wo3_kernel(const float* __restrict__ Wo) {
    __shared__ float t[32][33];
    const int n0 = blockIdx.x * 32, k0 = blockIdx.y * 32;
    const int tx = threadIdx.x, ty = threadIdx.y;
    for (int r = ty; r < 32; r += 8)
        t[r][tx] = Wo[(ull)(k0 + r) * HID + n0 + tx];
    __syncthreads();
    for (int r = ty; r < 32; r += 8) {
        __nv_bfloat16 h, l;
        split2(t[tx][r], h, l);
        __nv_bfloat16* p = g_wo3 + (ull)(n0 + r) * K3 + 3 * (k0 + tx);
        p[0] = h; p[1] = l; p[2] = h;
    }
}

// ================= HMMA GEMM (verified R7) =================
#define CHK     64
#define NCHUNK  (K3 / CHK)          // 72
#define TILE_B  16384
#define GEMM_SMEM (4 * TILE_B)

__global__ __launch_bounds__(256, 2) void hmma_gemm_kernel(
    int mode, float* __restrict__ outp,
    const float* __restrict__ bq, const float* __restrict__ bk, const float* __restrict__ bv)
{
    extern __shared__ __align__(1024) char dynsm[];
    const uint32_t sbase = smem_u32(dynsm);
    const int tid  = threadIdx.x;
    const int lane = tid & 31;
    const int wid  = tid >> 5;
    const int wm   = wid >> 2;
    const int wn   = wid & 3;
    const int m0   = blockIdx.y * 128;
    const int n0   = blockIdx.x * 128;

    const __nv_bfloat16* __restrict__ A3 = (mode == 0) ? g_x3 : g_at3;
    const __nv_bfloat16* __restrict__ B3 = (mode == 0) ? g_w3 : g_wo3;

    float d[4][4][4];
#pragma unroll
    for (int mi = 0; mi < 4; mi++)
#pragma unroll
        for (int ni = 0; ni < 4; ni++)
#pragma unroll
            for (int r = 0; r < 4; r++) d[mi][ni][r] = 0.f;

    const int lr = tid >> 3;
    const int lg = tid & 7;

    {
        const uint32_t sA = sbase, sB = sbase + TILE_B;
#pragma unroll
        for (int it = 0; it < 4; it++) {
            const int r = lr + it * 32;
            const uint32_t so = SWZ128((uint32_t)(r * 128 + lg * 16));
            cp_async16(sA + so, A3 + (ull)(m0 + r) * K3 + lg * 8);
            cp_async16(sB + so, B3 + (ull)(n0 + r) * K3 + lg * 8);
        }
        cp_commit();
    }

    const int arow = wm * 64 + (lane & 15);
    const int acol = (lane & 16) ? 16 : 0;
    const int brow = wn * 32 + (lane & 7) + ((lane & 16) ? 8 : 0);
    const int bcol = (lane & 8) ? 16 : 0;

    for (int c = 0; c < NCHUNK; c++) {
        cp_wait0();
        __syncthreads();
        if (c + 1 < NCHUNK) {
            const uint32_t nb = ((c + 1) & 1) ? 2u * TILE_B : 0u;
            const uint32_t sA = sbase + nb, sB = sbase + nb + TILE_B;
            const int k0 = (c + 1) * CHK;
#pragma unroll
            for (int it = 0; it < 4; it++) {
                const int r = lr + it * 32;
                const uint32_t so = SWZ128((uint32_t)(r * 128 + lg * 16));
                cp_async16(sA + so, A3 + (ull)(m0 + r) * K3 + k0 + lg * 8);
                cp_async16(sB + so, B3 + (ull)(n0 + r) * K3 + k0 + lg * 8);
            }
            cp_commit();
        }
        const uint32_t cb = (c & 1) ? 2u * TILE_B : 0u;
        const uint32_t sA = sbase + cb, sB = sbase + cb + TILE_B;
#pragma unroll
        for (int kk = 0; kk < 4; kk++) {
            uint32_t a[4][4], bb[4][2];
#pragma unroll
            for (int mi = 0; mi < 4; mi++)
                ldsm4(a[mi], sA + SWZ128((uint32_t)((arow + mi * 16) * 128 + kk * 32 + acol)));
            {
                uint32_t t4[4];
                ldsm4(t4, sB + SWZ128((uint32_t)(brow * 128 + kk * 32 + bcol)));
                bb[0][0] = t4[0]; bb[0][1] = t4[1]; bb[1][0] = t4[2]; bb[1][1] = t4[3];
                ldsm4(t4, sB + SWZ128((uint32_t)((brow + 16) * 128 + kk * 32 + bcol)));
                bb[2][0] = t4[0]; bb[2][1] = t4[1]; bb[3][0] = t4[2]; bb[3][1] = t4[3];
            }
#pragma unroll
            for (int mi = 0; mi < 4; mi++)
#pragma unroll
                for (int ni = 0; ni < 4; ni++)
                    mma16816(d[mi][ni], a[mi], bb[ni]);
        }
        __syncthreads();
    }

    float* dst; int ldc; const float* bias; int coff;
    if (mode == 1)        { dst = outp; ldc = HID;       bias = nullptr;          coff = n0; }
    else if (n0 < 1536)   { dst = g_q;  ldc = HID;       bias = bq + n0;          coff = n0; }
    else if (n0 < 1792)   { dst = g_kn; ldc = NKVH * HD; bias = bk + (n0 - 1536); coff = n0 - 1536; }
    else                  { dst = g_vn; ldc = NKVH * HD; bias = bv + (n0 - 1792); coff = n0 - 1792; }

#pragma unroll
    for (int mi = 0; mi < 4; mi++) {
        const int r0 = m0 + wm * 64 + mi * 16 + (lane >> 2);
#pragma unroll
        for (int ni = 0; ni < 4; ni++) {
            const int cl = wn * 32 + ni * 8 + (lane & 3) * 2;
            float b0 = 0.f, b1 = 0.f;
            if (bias) { b0 = bias[cl]; b1 = bias[cl + 1]; }
            float2 v0 = { d[mi][ni][0] + b0, d[mi][ni][1] + b1 };
            float2 v1 = { d[mi][ni][2] + b0, d[mi][ni][3] + b1 };
            *(float2*)(dst + (ull)r0 * ldc + coff + cl)       = v0;
            *(float2*)(dst + (ull)(r0 + 8) * ldc + coff + cl) = v1;
        }
    }
}

// ---------------- RoPE on Q -> g_q3 triplets ----------------
__global__ void rope_q_kernel(const float* __restrict__ fcos, const float* __restrict__ fsin)
{
    const int t = blockIdx.x;
    const int h = threadIdx.x >> 6;
    const int i = threadIdx.x & 63;
    const float* q = g_q + (ull)t * HID + h * HD;
    const float c = fcos[t * 64 + i];
    const float s = fsin[t * 64 + i];
    const float x1 = q[i];
    const float x2 = q[i + 64];
    const float r1 = x1 * c - x2 * s;
    const float r2 = x1 * s + x2 * c;
    __nv_bfloat16 h1, l1, h2, l2;
    split2(r1, h1, l1); split2(r2, h2, l2);
    __nv_bfloat16* dst = g_q3 + ((ull)h * QL + t) * D3;
    __nv_bfloat16* p1 = dst + 3 * i;
    p1[0] = h1; p1[1] = h1; p1[2] = l1;      // A-side (h,h,l)
    __nv_bfloat16* p2 = dst + 3 * (i + 64);
    p2[0] = h2; p2[1] = h2; p2[2] = l2;
}

// ---------------- build full K (triplets) + V (f32) ----------------
__global__ void build_kv_kernel(
    const float* __restrict__ k_hist, const float* __restrict__ v_hist,
    const float* __restrict__ fcos, const float* __restrict__ fsin)
{
    const int pos = blockIdx.x;
    const int kv = blockIdx.y;
    const int i = threadIdx.x;   // 0..63
    __nv_bfloat16* kd = g_k3 + ((ull)(kv * KLEN + pos)) * D3;
    float* vd = g_v + ((ull)(kv * KLEN + pos)) * HD;
    float k1, k2;
    if (pos < HISTL) {
        const float* ks = k_hist + ((ull)pos * NKVH + kv) * HD;
        const float* vs = v_hist + ((ull)pos * NKVH + kv) * HD;
        k1 = ks[i]; k2 = ks[i + 64];
        vd[i] = vs[i]; vd[i + 64] = vs[i + 64];
    } else {
        const int t = pos - HISTL;
        const float* ks = g_kn + (ull)t * (NKVH * HD) + kv * HD;
        const float* vs = g_vn + (ull)t * (NKVH * HD) + kv * HD;
        const float c = fcos[t * 64 + i];
        const float s = fsin[t * 64 + i];
        const float x1 = ks[i];
        const float x2 = ks[i + 64];
        k1 = x1 * c - x2 * s;
        k2 = x1 * s + x2 * c;
        vd[i] = vs[i]; vd[i + 64] = vs[i + 64];
    }
    __nv_bfloat16 h1, l1, h2, l2;
    split2(k1, h1, l1); split2(k2, h2, l2);
    __nv_bfloat16* p1 = kd + 3 * i;
    p1[0] = h1; p1[1] = l1; p1[2] = h1;      // B-side (h,l,h)
    __nv_bfloat16* p2 = kd + 3 * (i + 64);
    p2[0] = h2; p2[1] = l2; p2[2] = h2;
}

// ---------------- transpose V -> g_vt3 triplets ----------------
// grid(KLEN/32, HD/32, NKVH), block(32,8)
__global__ void vt3_kernel() {
    __shared__ float t[32][33];
    const int pos0 = blockIdx.x * 32, d0 = blockIdx.y * 32, kv = blockIdx.z;
    const int tx = threadIdx.x, ty = threadIdx.y;
    for (int r = ty; r < 32; r += 8)
        t[r][tx] = g_v[((ull)(kv * KLEN + pos0 + r)) * HD + d0 + tx];
    __syncthreads();
    for (int r = ty; r < 32; r += 8) {
        const float v = t[tx][r];
        __nv_bfloat16 h, l;
        split2(v, h, l);
        __nv_bfloat16* dst = g_vt3 + ((ull)(kv * HD + d0 + r)) * (3 * KLEN) + 3 * (pos0 + tx);
        dst[0] = h; dst[1] = l; dst[2] = h;  // B-side (h,l,h)
    }
}

// ================= HMMA flash attention =================
// CTA: 64q x 64k tiles, 8 warps (wm 0..1, wn 0..3). Triplet-compensated bf16.
// SMEM layout (bytes):
#define QS_STR 784
#define KS_STR 784
#define VS_STR 400
#define PS_STR 400
#define OFF_Q   0
#define OFF_K   50176
#define OFF_V   100352                  // 2 bufs x 51200
#define OFF_P   202752
#define OFF_RM  228352                  // redmax [4][64] f32
#define OFF_RS  229376                  // redsum [4][64] f32
#define ATT_SMEM 230400

__global__ __launch_bounds__(256, 1) void attention_kernel()
{
    extern __shared__ __align__(1024) char asmem[];
    const uint32_t sb = smem_u32(asmem);
    const int h  = blockIdx.x;
    const int qb = 31 - blockIdx.y;
    const int kvh = h / GRP;
    const int q0 = qb * 64;
    const int tid = threadIdx.x;
    const int lane = tid & 31;
    const int wid = tid >> 5;
    const int wm = wid >> 2;      // 0..1
    const int wn = wid & 3;       // 0..3
    const int n_tiles = qb + 33;

    const __nv_bfloat16* Qg = g_q3 + ((ull)h * QL + q0) * D3;
    const __nv_bfloat16* Kg = g_k3 + ((ull)kvh * KLEN) * D3;
    const __nv_bfloat16* Vg = g_vt3 + ((ull)kvh * HD) * (3 * KLEN);

    // ---- prologue: load Q tile + K[0] + V[0] ----
    for (int u = tid; u < 64 * 48; u += 256) {
        const int r = u / 48, c = u % 48;
        cp_async16(sb + OFF_Q + r * QS_STR + c * 16, Qg + (ull)r * D3 + c * 8);
        cp_async16(sb + OFF_K + r * KS_STR + c * 16, Kg + (ull)r * D3 + c * 8);
    }
    for (int u = tid; u < 128 * 24; u += 256) {
        const int r = u / 24, c = u % 24;
        cp_async16(sb + OFF_V + r * VS_STR + c * 16, Vg + (ull)r * (3 * KLEN) + c * 8);
    }
    cp_commit();

    float accO[2][4][4];
    float mrow[2][2], lrow[2][2];
#pragma unroll
    for (int mi = 0; mi < 2; mi++) {
#pragma unroll
        for (int hf = 0; hf < 2; hf++) { mrow[mi][hf] = -1e30f; lrow[mi][hf] = 0.f; }
#pragma unroll
        for (int ni = 0; ni < 4; ni++)
#pragma unroll
            for (int r = 0; r < 4; r++) accO[mi][ni][r] = 0.f;
    }

    const int arow = wm * 32 + (lane & 15);
    const int acol = (lane & 16) ? 16 : 0;
    const int qbrow = wn * 16 + (lane & 7) + ((lane & 16) ? 8 : 0);
    const int vbrow = wn * 32 + (lane & 7) + ((lane & 16) ? 8 : 0);
    const int kbcol = (lane & 8) ? 16 : 0;

    for (int kt = 0; kt < n_tiles; kt++) {
        cp_wait0();
        __syncthreads();

        // ---- S = Q K^T over d3 = 384 ----
        float S[2][2][4];
#pragma unroll
        for (int mi = 0; mi < 2; mi++)
#pragma unroll
            for (int nf = 0; nf < 2; nf++)
#pragma unroll
                for (int r = 0; r < 4; r++) S[mi][nf][r] = 0.f;

#pragma unroll 4
        for (int kk = 0; kk < 24; kk++) {
            uint32_t a0[4], a1[4], t4[4];
            ldsm4(a0, sb + OFF_Q + (uint32_t)(arow * QS_STR + kk * 32 + acol));
            ldsm4(a1, sb + OFF_Q + (uint32_t)((arow + 16) * QS_STR + kk * 32 + acol));
            ldsm4(t4, sb + OFF_K + (uint32_t)(qbrow * KS_STR + kk * 32 + kbcol));
            mma16816(S[0][0], a0, &t4[0]);
            mma16816(S[0][1], a0, &t4[2]);
            mma16816(S[1][0], a1, &t4[0]);
            mma16816(S[1][1], a1, &t4[2]);
        }

        // ---- scale + mask + row max (partial) ----
        const int kb = kt * 64;
        const bool maskt = (kt == qb + 32);
        float mloc[2][2];
#pragma unroll
        for (int mi = 0; mi < 2; mi++)
#pragma unroll
            for (int hf = 0; hf < 2; hf++) mloc[mi][hf] = -1e30f;
#pragma unroll
        for (int mi = 0; mi < 2; mi++)
#pragma unroll
            for (int nf = 0; nf < 2; nf++)
#pragma unroll
                for (int r = 0; r < 4; r++) {
                    float s = S[mi][nf][r] * 0.08838834764831845f;
                    if (maskt) {
                        const int hf = r >> 1;
                        const int qg = q0 + wm * 32 + mi * 16 + (lane >> 2) + hf * 8;
                        const int kg = kb + wn * 16 + nf * 8 + (lane & 3) * 2 + (r & 1);
                        if (kg > qg + HISTL) s = -1e30f;
                    }
                    S[mi][nf][r] = s;
                    const int hf = r >> 1;
                    mloc[mi][hf] = fmaxf(mloc[mi][hf], s);
                }
#pragma unroll
        for (int mi = 0; mi < 2; mi++)
#pragma unroll
            for (int hf = 0; hf < 2; hf++) {
                float v = mloc[mi][hf];
                v = fmaxf(v, __shfl_xor_sync(0xffffffffu, v, 1));
                v = fmaxf(v, __shfl_xor_sync(0xffffffffu, v, 2));
                mloc[mi][hf] = v;
            }
        if ((lane & 3) == 0) {
            float* rm = (float*)(asmem + (OFF_RM - 0)) ;
#pragma unroll
            for (int mi = 0; mi < 2; mi++)
#pragma unroll
                for (int hf = 0; hf < 2; hf++)
                    rm[wn * 64 + wm * 32 + mi * 16 + hf * 8 + (lane >> 2)] = mloc[mi][hf];
        }
        __syncthreads();

        // ---- prefetch next tile (K safe: all warps past QK; V other buf) ----
        if (kt + 1 < n_tiles) {
            const int kb2 = (kt + 1) * 64;
            for (int u = tid; u < 64 * 48; u += 256) {
                const int r = u / 48, c = u % 48;
                cp_async16(sb + OFF_K + r * KS_STR + c * 16,
                           Kg + (ull)(kb2 + r) * D3 + c * 8);
            }
            const uint32_t vbuf = sb + OFF_V + ((kt + 1) & 1) * 51200;
            for (int u = tid; u < 128 * 24; u += 256) {
                const int r = u / 24, c = u % 24;
                cp_async16(vbuf + r * VS_STR + c * 16,
                           Vg + (ull)r * (3 * KLEN) + 3 * kb2 + c * 8);
            }
            cp_commit();
        }

        // ---- combine max, exp, write P3 triplets, partial sums ----
        float* rm = (float*)(asmem + OFF_RM);
        float* rs = (float*)(asmem + OFF_RS);
        float corr[2][2], mnew[2][2], sloc[2][2];
#pragma unroll
        for (int mi = 0; mi < 2; mi++)
#pragma unroll
            for (int hf = 0; hf < 2; hf++) {
                const int row = wm * 32 + mi * 16 + hf * 8 + (lane >> 2);
                float v = mrow[mi][hf];
                v = fmaxf(v, rm[0 * 64 + row]);
                v = fmaxf(v, rm[1 * 64 + row]);
                v = fmaxf(v, rm[2 * 64 + row]);
                v = fmaxf(v, rm[3 * 64 + row]);
                mnew[mi][hf] = v;
                corr[mi][hf] = __expf(mrow[mi][hf] - v);
                mrow[mi][hf] = v;
                sloc[mi][hf] = 0.f;
            }
#pragma unroll
        for (int mi = 0; mi < 2; mi++)
#pragma unroll
            for (int nf = 0; nf < 2; nf++) {
#pragma unroll
                for (int hf = 0; hf < 2; hf++) {
                    const float p0 = __expf(S[mi][nf][hf * 2 + 0] - mnew[mi][hf]);
                    const float p1 = __expf(S[mi][nf][hf * 2 + 1] - mnew[mi][hf]);
                    sloc[mi][hf] += p0 + p1;
                    // triplet pack: (h0,h0,l0,h1,h1,l1)
                    __nv_bfloat16 h0, l0, h1, l1;
                    split2(p0, h0, l0); split2(p1, h1, l1);
                    const int row = wm * 32 + mi * 16 + hf * 8 + (lane >> 2);
                    const int c2 = wn * 16 + nf * 8 + (lane & 3) * 2;
                    uint32_t* dp = (uint32_t*)(asmem + OFF_P + row * PS_STR + 6 * c2);
                    dp[0] = bfpack(h0, h0);
                    dp[1] = bfpack(l0, h1);
                    dp[2] = bfpack(h1, l1);
                }
            }
#pragma unroll
        for (int mi = 0; mi < 2; mi++)
#pragma unroll
            for (int hf = 0; hf < 2; hf++) {
                float v = sloc[mi][hf];
                v += __shfl_xor_sync(0xffffffffu, v, 1);
                v += __shfl_xor_sync(0xffffffffu, v, 2);
                sloc[mi][hf] = v;
            }
        if ((lane & 3) == 0) {
#pragma unroll
            for (int mi = 0; mi < 2; mi++)
#pragma unroll
                for (int hf = 0; hf < 2; hf++)
                    rs[wn * 64 + wm * 32 + mi * 16 + hf * 8 + (lane >> 2)] = sloc[mi][hf];
        }
        // rescale O accumulators
#pragma unroll
        for (int mi = 0; mi < 2; mi++)
#pragma unroll
            for (int ni = 0; ni < 4; ni++) {
                accO[mi][ni][0] *= corr[mi][0];
                accO[mi][ni][1] *= corr[mi][0];
                accO[mi][ni][2] *= corr[mi][1];
                accO[mi][ni][3] *= corr[mi][1];
            }
        __syncthreads();   // P3 + reds ready
#pragma unroll
        for (int mi = 0; mi < 2; mi++)
#pragma unroll
            for (int hf = 0; hf < 2; hf++) {
                const int row = wm * 32 + mi * 16 + hf * 8 + (lane >> 2);
                lrow[mi][hf] = lrow[mi][hf] * corr[mi][hf]
                    + rs[0 * 64 + row] + rs[1 * 64 + row] + rs[2 * 64 + row] + rs[3 * 64 + row];
            }

        // ---- O += P3 @ Vt3 over k3 = 192 ----
        const uint32_t sP = sb + OFF_P;
        const uint32_t sV = sb + OFF_V + (kt & 1) * 51200;
#pragma unroll 3
        for (int kk = 0; kk < 12; kk++) {
            uint32_t pa0[4], pa1[4], v0[4], v1[4];
            ldsm4(pa0, sP + (uint32_t)(arow * PS_STR + kk * 32 + acol));
            ldsm4(pa1, sP + (uint32_t)((arow + 16) * PS_STR + kk * 32 + acol));
            ldsm4(v0, sV + (uint32_t)(vbrow * VS_STR + kk * 32 + kbcol));
            ldsm4(v1, sV + (uint32_t)((vbrow + 16) * VS_STR + kk * 32 + kbcol));
            mma16816(accO[0][0], pa0, &v0[0]);
            mma16816(accO[0][1], pa0, &v0[2]);
            mma16816(accO[0][2], pa0, &v1[0]);
            mma16816(accO[0][3], pa0, &v1[2]);
            mma16816(accO[1][0], pa1, &v0[0]);
            mma16816(accO[1][1], pa1, &v0[2]);
            mma16816(accO[1][2], pa1, &v1[0]);
            mma16816(accO[1][3], pa1, &v1[2]);
        }
        // loop-top sync orders PV reads vs next tile's P3 writes
    }

    // ---- epilogue: normalize, write g_at3 triplets (A-side h,h,l) ----
#pragma unroll
    for (int mi = 0; mi < 2; mi++) {
#pragma unroll
        for (int hf = 0; hf < 2; hf++) {
            const float inv = 1.f / lrow[mi][hf];
            const int row = q0 + wm * 32 + mi * 16 + hf * 8 + (lane >> 2);
#pragma unroll
            for (int ni = 0; ni < 4; ni++) {
                const int dcol = wn * 32 + ni * 8 + (lane & 3) * 2;
                const float v0 = accO[mi][ni][hf * 2 + 0] * inv;
                const float v1 = accO[mi][ni][hf * 2 + 1] * inv;
                __nv_bfloat16 h0, l0, h1, l1;
                split2(v0, h0, l0); split2(v1, h1, l1);
                uint32_t* dp = (uint32_t*)(g_at3 + (ull)row * K3 + 3 * (h * HD + dcol));
                dp[0] = bfpack(h0, h0);
                dp[1] = bfpack(l0, h1);
                dp[2] = bfpack(h1, l1);
            }
        }
    }
}

// ---------------- launch ----------------
extern "C" void kernel_launch(void* const* d_in, const int* in_sizes, int n_in,
                              void* d_out, int out_size)
{
    const float* x     = (const float*)d_in[0];
    const float* Wq    = (const float*)d_in[1];
    const float* bq    = (const float*)d_in[2];
    const float* Wk    = (const float*)d_in[3];
    const float* bk    = (const float*)d_in[4];
    const float* Wv    = (const float*)d_in[5];
    const float* bv    = (const float*)d_in[6];
    const float* Wo    = (const float*)d_in[7];
    const float* khist = (const float*)d_in[8];
    const float* vhist = (const float*)d_in[9];
    const float* fcos  = (const float*)d_in[10];
    const float* fsin  = (const float*)d_in[11];
    float* out = (float*)d_out;

    cudaFuncSetAttribute(attention_kernel,
                         cudaFuncAttributeMaxDynamicSharedMemorySize, ATT_SMEM);
    cudaFuncSetAttribute(hmma_gemm_kernel,
                         cudaFuncAttributeMaxDynamicSharedMemorySize, GEMM_SMEM);

    conv_x3_kernel<<<QL * HID / 256, 256>>>(x);
    conv_wqkv3_kernel<<<dim3(64, 48), dim3(32, 8)>>>(Wq, Wk, Wv);
    conv_wo3_kernel<<<dim3(48, 48), dim3(32, 8)>>>(Wo);

    hmma_gemm_kernel<<<dim3(16, 16), 256, GEMM_SMEM>>>(0, nullptr, bq, bk, bv);

    rope_q_kernel<<<QL, NH * 64>>>(fcos, fsin);
    build_kv_kernel<<<dim3(KLEN, NKVH), 64>>>(khist, vhist, fcos, fsin);
    vt3_kernel<<<dim3(KLEN / 32, HD / 32, NKVH), dim3(32, 8)>>>();

    attention_kernel<<<dim3(NH, 32), 256, ATT_SMEM>>>();

    hmma_gemm_kernel<<<dim3(12, 16), 256, GEMM_SMEM>>>(1, out, nullptr, nullptr, nullptr);
}

// round 9
// speedup vs baseline: 3.7527x; 1.0396x over previous
#include <cuda_runtime.h>
#include <cuda_bf16.h>
#include <cstdint>

typedef unsigned long long ull;

#define QL    2048
#define HISTL 2048
#define KLEN  4096
#define NH    12
#define NKVH  2
#define HD    128
#define HID   1536
#define GRP   6
#define K3    4608           // 3 * 1536 (hi/lo compensated K extension)
#define D3    384            // 3 * 128

// ---------------- scratch (static device globals; no allocation) ----------------
__device__ float g_q[QL * HID];          // Q projection (pre-RoPE, f32)
__device__ float g_kn[QL * NKVH * HD];   // new K projection (pre-RoPE)
__device__ float g_vn[QL * NKVH * HD];   // new V projection
__device__ float g_v[NKVH * KLEN * HD];  // full V (f32, for transpose)

// bf16 triplet operands
__device__ __nv_bfloat16 g_x3[QL * K3];          // x triplets (A: h,h,l)
__device__ __nv_bfloat16 g_w3[2048 * K3];        // [Wq|Wk|Wv]^T triplets (B: h,l,h)
__device__ __nv_bfloat16 g_wo3[HID * K3];        // Wo^T triplets (B)
__device__ __nv_bfloat16 g_at3[QL * K3];         // attention out triplets (A)
__device__ __nv_bfloat16 g_q3[NH * QL * D3];     // RoPE'd Q triplets (A)
__device__ __nv_bfloat16 g_k3[NKVH * KLEN * D3]; // full K triplets (B)
__device__ __nv_bfloat16 g_vt3[NKVH * HD * (3 * KLEN)]; // V^T triplets (B)

// ---------------- helpers ----------------
__device__ __forceinline__ uint32_t smem_u32(const void* p) {
    uint32_t a;
    asm("{ .reg .u64 t; cvta.to.shared.u64 t, %1; cvt.u32.u64 %0, t; }" : "=r"(a) : "l"(p));
    return a;
}
#define SWZ128(off) ((off) ^ (((off) >> 3) & 0x70))

__device__ __forceinline__ void ldsm4(uint32_t* r, uint32_t addr) {
    asm volatile("ldmatrix.sync.aligned.m8n8.x4.shared.b16 {%0,%1,%2,%3}, [%4];"
        : "=r"(r[0]), "=r"(r[1]), "=r"(r[2]), "=r"(r[3]) : "r"(addr));
}
__device__ __forceinline__ void mma16816(float* d, const uint32_t* a, const uint32_t* b) {
    asm volatile("mma.sync.aligned.m16n8k16.row.col.f32.bf16.bf16.f32 "
        "{%0,%1,%2,%3},{%4,%5,%6,%7},{%8,%9},{%0,%1,%2,%3};"
        : "+f"(d[0]), "+f"(d[1]), "+f"(d[2]), "+f"(d[3])
        : "r"(a[0]), "r"(a[1]), "r"(a[2]), "r"(a[3]), "r"(b[0]), "r"(b[1]));
}
__device__ __forceinline__ void cp_async16(uint32_t saddr, const void* gptr) {
    asm volatile("cp.async.cg.shared.global [%0], [%1], 16;"
        :: "r"(saddr), "l"((size_t)__cvta_generic_to_global(gptr)) : "memory");
}
__device__ __forceinline__ void cp_commit() { asm volatile("cp.async.commit_group;" ::: "memory"); }
__device__ __forceinline__ void cp_wait0()  { asm volatile("cp.async.wait_group 0;" ::: "memory"); }
__device__ __forceinline__ void cp_wait1()  { asm volatile("cp.async.wait_group 1;" ::: "memory"); }

__device__ __forceinline__ void split2(float v, __nv_bfloat16& h, __nv_bfloat16& l) {
    h = __float2bfloat16(v);
    l = __float2bfloat16(v - __bfloat162float(h));
}
__device__ __forceinline__ uint32_t bfpack(__nv_bfloat16 a, __nv_bfloat16 b) {
    return (uint32_t)__bfloat16_as_ushort(a) | ((uint32_t)__bfloat16_as_ushort(b) << 16);
}

// ================= conversion kernels =================
__global__ void conv_x3_kernel(const float* __restrict__ src) {
    const int i = blockIdx.x * blockDim.x + threadIdx.x;
    const int m = i / HID, k = i % HID;
    __nv_bfloat16 h, l;
    split2(src[i], h, l);
    __nv_bfloat16* p = g_x3 + (ull)m * K3 + 3 * k;
    p[0] = h; p[1] = h; p[2] = l;
}

__global__ void conv_wqkv3_kernel(const float* __restrict__ Wq,
                                  const float* __restrict__ Wk,
                                  const float* __restrict__ Wv) {
    __shared__ float t[32][33];
    const int n0 = blockIdx.x * 32, k0 = blockIdx.y * 32;
    const int tx = threadIdx.x, ty = threadIdx.y;
    const float* W; int nb, ld;
    if (n0 < 1536)      { W = Wq; nb = n0;        ld = HID; }
    else if (n0 < 1792) { W = Wk; nb = n0 - 1536; ld = NKVH * HD; }
    else                { W = Wv; nb = n0 - 1792; ld = NKVH * HD; }
    for (int r = ty; r < 32; r += 8)
        t[r][tx] = W[(ull)(k0 + r) * ld + nb + tx];
    __syncthreads();
    for (int r = ty; r < 32; r += 8) {
        __nv_bfloat16 h, l;
        split2(t[tx][r], h, l);
        __nv_bfloat16* p = g_w3 + (ull)(n0 + r) * K3 + 3 * (k0 + tx);
        p[0] = h; p[1] = l; p[2] = h;
    }
}

__global__ void conv_wo3_kernel(const float* __restrict__ Wo) {
    __shared__ float t[32][33];
    const int n0 = blockIdx.x * 32, k0 = blockIdx.y * 32;
    const int tx = threadIdx.x, ty = threadIdx.y;
    for (int r = ty; r < 32; r += 8)
        t[r][tx] = Wo[(ull)(k0 + r) * HID + n0 + tx];
    __syncthreads();
    for (int r = ty; r < 32; r += 8) {
        __nv_bfloat16 h, l;
        split2(t[tx][r], h, l);
        __nv_bfloat16* p = g_wo3 + (ull)(n0 + r) * K3 + 3 * (k0 + tx);
        p[0] = h; p[1] = l; p[2] = h;
    }
}

// ================= HMMA GEMM (3-stage cp.async pipeline) =================
#define CHK     64
#define NCHUNK  (K3 / CHK)          // 72
#define TILE_B  16384
#define NBUF    3
#define GEMM_SMEM (NBUF * 2 * TILE_B)   // 98304

__global__ __launch_bounds__(256, 2) void hmma_gemm_kernel(
    int mode, float* __restrict__ outp,
    const float* __restrict__ bq, const float* __restrict__ bk, const float* __restrict__ bv)
{
    extern __shared__ __align__(1024) char dynsm[];
    const uint32_t sbase = smem_u32(dynsm);
    const int tid  = threadIdx.x;
    const int lane = tid & 31;
    const int wid  = tid >> 5;
    const int wm   = wid >> 2;
    const int wn   = wid & 3;
    const int m0   = blockIdx.y * 128;
    const int n0   = blockIdx.x * 128;

    const __nv_bfloat16* __restrict__ A3 = (mode == 0) ? g_x3 : g_at3;
    const __nv_bfloat16* __restrict__ B3 = (mode == 0) ? g_w3 : g_wo3;

    float d[4][4][4];
#pragma unroll
    for (int mi = 0; mi < 4; mi++)
#pragma unroll
        for (int ni = 0; ni < 4; ni++)
#pragma unroll
            for (int r = 0; r < 4; r++) d[mi][ni][r] = 0.f;

    const int lr = tid >> 3;
    const int lg = tid & 7;

    // prologue: chunks 0,1 -> bufs 0,1 (one commit group each)
#pragma unroll
    for (int pc = 0; pc < 2; pc++) {
        const uint32_t sA = sbase + pc * (2u * TILE_B), sB = sA + TILE_B;
        const int k0 = pc * CHK;
#pragma unroll
        for (int it = 0; it < 4; it++) {
            const int r = lr + it * 32;
            const uint32_t so = SWZ128((uint32_t)(r * 128 + lg * 16));
            cp_async16(sA + so, A3 + (ull)(m0 + r) * K3 + k0 + lg * 8);
            cp_async16(sB + so, B3 + (ull)(n0 + r) * K3 + k0 + lg * 8);
        }
        cp_commit();
    }

    const int arow = wm * 64 + (lane & 15);
    const int acol = (lane & 16) ? 16 : 0;
    const int brow = wn * 32 + (lane & 7) + ((lane & 16) ? 8 : 0);
    const int bcol = (lane & 8) ? 16 : 0;

    int ldbuf = 2;     // next buffer to fill
    for (int c = 0; c < NCHUNK; c++) {
        cp_wait1();            // chunk c landed (c+1 may still be in flight)
        __syncthreads();
        if (c + 2 < NCHUNK) {
            const uint32_t sA = sbase + (uint32_t)ldbuf * (2u * TILE_B), sB = sA + TILE_B;
            const int k0 = (c + 2) * CHK;
#pragma unroll
            for (int it = 0; it < 4; it++) {
                const int r = lr + it * 32;
                const uint32_t so = SWZ128((uint32_t)(r * 128 + lg * 16));
                cp_async16(sA + so, A3 + (ull)(m0 + r) * K3 + k0 + lg * 8);
                cp_async16(sB + so, B3 + (ull)(n0 + r) * K3 + k0 + lg * 8);
            }
            cp_commit();
            if (++ldbuf == NBUF) ldbuf = 0;
        }
        const uint32_t cb = (uint32_t)(c % NBUF) * (2u * TILE_B);
        const uint32_t sA = sbase + cb, sB = sbase + cb + TILE_B;
#pragma unroll
        for (int kk = 0; kk < 4; kk++) {
            uint32_t a[4][4], bb[4][2];
#pragma unroll
            for (int mi = 0; mi < 4; mi++)
                ldsm4(a[mi], sA + SWZ128((uint32_t)((arow + mi * 16) * 128 + kk * 32 + acol)));
            {
                uint32_t t4[4];
                ldsm4(t4, sB + SWZ128((uint32_t)(brow * 128 + kk * 32 + bcol)));
                bb[0][0] = t4[0]; bb[0][1] = t4[1]; bb[1][0] = t4[2]; bb[1][1] = t4[3];
                ldsm4(t4, sB + SWZ128((uint32_t)((brow + 16) * 128 + kk * 32 + bcol)));
                bb[2][0] = t4[0]; bb[2][1] = t4[1]; bb[3][0] = t4[2]; bb[3][1] = t4[3];
            }
#pragma unroll
            for (int mi = 0; mi < 4; mi++)
#pragma unroll
                for (int ni = 0; ni < 4; ni++)
                    mma16816(d[mi][ni], a[mi], bb[ni]);
        }
        __syncthreads();
    }

    float* dst; int ldc; const float* bias; int coff;
    if (mode == 1)        { dst = outp; ldc = HID;       bias = nullptr;          coff = n0; }
    else if (n0 < 1536)   { dst = g_q;  ldc = HID;       bias = bq + n0;          coff = n0; }
    else if (n0 < 1792)   { dst = g_kn; ldc = NKVH * HD; bias = bk + (n0 - 1536); coff = n0 - 1536; }
    else                  { dst = g_vn; ldc = NKVH * HD; bias = bv + (n0 - 1792); coff = n0 - 1792; }

#pragma unroll
    for (int mi = 0; mi < 4; mi++) {
        const int r0 = m0 + wm * 64 + mi * 16 + (lane >> 2);
#pragma unroll
        for (int ni = 0; ni < 4; ni++) {
            const int cl = wn * 32 + ni * 8 + (lane & 3) * 2;
            float b0 = 0.f, b1 = 0.f;
            if (bias) { b0 = bias[cl]; b1 = bias[cl + 1]; }
            float2 v0 = { d[mi][ni][0] + b0, d[mi][ni][1] + b1 };
            float2 v1 = { d[mi][ni][2] + b0, d[mi][ni][3] + b1 };
            *(float2*)(dst + (ull)r0 * ldc + coff + cl)       = v0;
            *(float2*)(dst + (ull)(r0 + 8) * ldc + coff + cl) = v1;
        }
    }
}

// ---------------- RoPE on Q -> g_q3 triplets ----------------
__global__ void rope_q_kernel(const float* __restrict__ fcos, const float* __restrict__ fsin)
{
    const int t = blockIdx.x;
    const int h = threadIdx.x >> 6;
    const int i = threadIdx.x & 63;
    const float* q = g_q + (ull)t * HID + h * HD;
    const float c = fcos[t * 64 + i];
    const float s = fsin[t * 64 + i];
    const float x1 = q[i];
    const float x2 = q[i + 64];
    const float r1 = x1 * c - x2 * s;
    const float r2 = x1 * s + x2 * c;
    __nv_bfloat16 h1, l1, h2, l2;
    split2(r1, h1, l1); split2(r2, h2, l2);
    __nv_bfloat16* dst = g_q3 + ((ull)h * QL + t) * D3;
    __nv_bfloat16* p1 = dst + 3 * i;
    p1[0] = h1; p1[1] = h1; p1[2] = l1;
    __nv_bfloat16* p2 = dst + 3 * (i + 64);
    p2[0] = h2; p2[1] = h2; p2[2] = l2;
}

// ---------------- build full K (triplets) + V (f32) ----------------
__global__ void build_kv_kernel(
    const float* __restrict__ k_hist, const float* __restrict__ v_hist,
    const float* __restrict__ fcos, const float* __restrict__ fsin)
{
    const int pos = blockIdx.x;
    const int kv = blockIdx.y;
    const int i = threadIdx.x;
    __nv_bfloat16* kd = g_k3 + ((ull)(kv * KLEN + pos)) * D3;
    float* vd = g_v + ((ull)(kv * KLEN + pos)) * HD;
    float k1, k2;
    if (pos < HISTL) {
        const float* ks = k_hist + ((ull)pos * NKVH + kv) * HD;
        const float* vs = v_hist + ((ull)pos * NKVH + kv) * HD;
        k1 = ks[i]; k2 = ks[i + 64];
        vd[i] = vs[i]; vd[i + 64] = vs[i + 64];
    } else {
        const int t = pos - HISTL;
        const float* ks = g_kn + (ull)t * (NKVH * HD) + kv * HD;
        const float* vs = g_vn + (ull)t * (NKVH * HD) + kv * HD;
        const float c = fcos[t * 64 + i];
        const float s = fsin[t * 64 + i];
        const float x1 = ks[i];
        const float x2 = ks[i + 64];
        k1 = x1 * c - x2 * s;
        k2 = x1 * s + x2 * c;
        vd[i] = vs[i]; vd[i + 64] = vs[i + 64];
    }
    __nv_bfloat16 h1, l1, h2, l2;
    split2(k1, h1, l1); split2(k2, h2, l2);
    __nv_bfloat16* p1 = kd + 3 * i;
    p1[0] = h1; p1[1] = l1; p1[2] = h1;
    __nv_bfloat16* p2 = kd + 3 * (i + 64);
    p2[0] = h2; p2[1] = l2; p2[2] = h2;
}

// ---------------- transpose V -> g_vt3 triplets ----------------
__global__ void vt3_kernel() {
    __shared__ float t[32][33];
    const int pos0 = blockIdx.x * 32, d0 = blockIdx.y * 32, kv = blockIdx.z;
    const int tx = threadIdx.x, ty = threadIdx.y;
    for (int r = ty; r < 32; r += 8)
        t[r][tx] = g_v[((ull)(kv * KLEN + pos0 + r)) * HD + d0 + tx];
    __syncthreads();
    for (int r = ty; r < 32; r += 8) {
        const float v = t[tx][r];
        __nv_bfloat16 h, l;
        split2(v, h, l);
        __nv_bfloat16* dst = g_vt3 + ((ull)(kv * HD + d0 + r)) * (3 * KLEN) + 3 * (pos0 + tx);
        dst[0] = h; dst[1] = l; dst[2] = h;
    }
}

// ================= HMMA flash attention (fixed-max softmax) =================
#define QS_STR 784
#define KS_STR 784
#define VS_STR 400
#define PS_STR 400
#define OFF_Q   0
#define OFF_K   50176
#define OFF_V   100352                  // 2 bufs x 51200
#define OFF_P   202752
#define OFF_RS  228352                  // row-sum combine [4][64] f32
#define ATT_SMEM 229376

__global__ __launch_bounds__(256, 1) void attention_kernel()
{
    extern __shared__ __align__(1024) char asmem[];
    const uint32_t sb = smem_u32(asmem);
    const int h  = blockIdx.x;
    const int qb = 31 - blockIdx.y;
    const int kvh = h / GRP;
    const int q0 = qb * 64;
    const int tid = threadIdx.x;
    const int lane = tid & 31;
    const int wid = tid >> 5;
    const int wm = wid >> 2;      // 0..1
    const int wn = wid & 3;       // 0..3
    const int n_tiles = qb + 33;

    const __nv_bfloat16* Qg = g_q3 + ((ull)h * QL + q0) * D3;
    const __nv_bfloat16* Kg = g_k3 + ((ull)kvh * KLEN) * D3;
    const __nv_bfloat16* Vg = g_vt3 + ((ull)kvh * HD) * (3 * KLEN);

    // ---- prologue: load Q tile + K[0] + V[0] ----
    for (int u = tid; u < 64 * 48; u += 256) {
        const int r = u / 48, c = u % 48;
        cp_async16(sb + OFF_Q + r * QS_STR + c * 16, Qg + (ull)r * D3 + c * 8);
        cp_async16(sb + OFF_K + r * KS_STR + c * 16, Kg + (ull)r * D3 + c * 8);
    }
    for (int u = tid; u < 128 * 24; u += 256) {
        const int r = u / 24, c = u % 24;
        cp_async16(sb + OFF_V + r * VS_STR + c * 16, Vg + (ull)r * (3 * KLEN) + c * 8);
    }
    cp_commit();

    float accO[2][4][4];
    float psum[2][2];
#pragma unroll
    for (int mi = 0; mi < 2; mi++) {
#pragma unroll
        for (int hf = 0; hf < 2; hf++) psum[mi][hf] = 0.f;
#pragma unroll
        for (int ni = 0; ni < 4; ni++)
#pragma unroll
            for (int r = 0; r < 4; r++) accO[mi][ni][r] = 0.f;
    }

    const int arow = wm * 32 + (lane & 15);
    const int acol = (lane & 16) ? 16 : 0;
    const int qbrow = wn * 16 + (lane & 7) + ((lane & 16) ? 8 : 0);
    const int vbrow = wn * 32 + (lane & 7) + ((lane & 16) ? 8 : 0);
    const int kbcol = (lane & 8) ? 16 : 0;

    for (int kt = 0; kt < n_tiles; kt++) {
        cp_wait0();
        __syncthreads();           // tile data ready; prev PV done

        // ---- S = Q K^T over d3 = 384 ----
        float S[2][2][4];
#pragma unroll
        for (int mi = 0; mi < 2; mi++)
#pragma unroll
            for (int nf = 0; nf < 2; nf++)
#pragma unroll
                for (int r = 0; r < 4; r++) S[mi][nf][r] = 0.f;

#pragma unroll 4
        for (int kk = 0; kk < 24; kk++) {
            uint32_t a0[4], a1[4], t4[4];
            ldsm4(a0, sb + OFF_Q + (uint32_t)(arow * QS_STR + kk * 32 + acol));
            ldsm4(a1, sb + OFF_Q + (uint32_t)((arow + 16) * QS_STR + kk * 32 + acol));
            ldsm4(t4, sb + OFF_K + (uint32_t)(qbrow * KS_STR + kk * 32 + kbcol));
            mma16816(S[0][0], a0, &t4[0]);
            mma16816(S[0][1], a0, &t4[2]);
            mma16816(S[1][0], a1, &t4[0]);
            mma16816(S[1][1], a1, &t4[2]);
        }
        __syncthreads();           // all warps done reading K/V SMEM... (K reread below prevented)

        // ---- prefetch next tile's K (+V alt buffer) ----
        if (kt + 1 < n_tiles) {
            const int kb2 = (kt + 1) * 64;
            for (int u = tid; u < 64 * 48; u += 256) {
                const int r = u / 48, c = u % 48;
                cp_async16(sb + OFF_K + r * KS_STR + c * 16,
                           Kg + (ull)(kb2 + r) * D3 + c * 8);
            }
            const uint32_t vbuf = sb + OFF_V + ((kt + 1) & 1) * 51200;
            for (int u = tid; u < 128 * 24; u += 256) {
                const int r = u / 24, c = u % 24;
                cp_async16(vbuf + r * VS_STR + c * 16,
                           Vg + (ull)r * (3 * KLEN) + 3 * kb2 + c * 8);
            }
            cp_commit();
        }

        // ---- scale + mask + exp (fixed max 0) + pack P3 + partial sums ----
        const int kb = kt * 64;
        const bool maskt = (kt == qb + 32);
#pragma unroll
        for (int mi = 0; mi < 2; mi++)
#pragma unroll
            for (int nf = 0; nf < 2; nf++)
#pragma unroll
                for (int hf = 0; hf < 2; hf++) {
                    float s0 = S[mi][nf][hf * 2 + 0] * 0.08838834764831845f;
                    float s1 = S[mi][nf][hf * 2 + 1] * 0.08838834764831845f;
                    if (maskt) {
                        const int qg = q0 + wm * 32 + mi * 16 + (lane >> 2) + hf * 8;
                        const int kg = kb + wn * 16 + nf * 8 + (lane & 3) * 2;
                        if (kg > qg + HISTL)     s0 = -1e30f;
                        if (kg + 1 > qg + HISTL) s1 = -1e30f;
                    }
                    const float p0 = __expf(s0);
                    const float p1 = __expf(s1);
                    psum[mi][hf] += p0 + p1;
                    __nv_bfloat16 h0, l0, h1, l1;
                    split2(p0, h0, l0); split2(p1, h1, l1);
                    const int row = wm * 32 + mi * 16 + hf * 8 + (lane >> 2);
                    const int c2 = wn * 16 + nf * 8 + (lane & 3) * 2;
                    uint32_t* dp = (uint32_t*)(asmem + OFF_P + row * PS_STR + 6 * c2);
                    dp[0] = bfpack(h0, h0);
                    dp[1] = bfpack(l0, h1);
                    dp[2] = bfpack(h1, l1);
                }
        __syncthreads();           // P3 ready

        // ---- O += P3 @ Vt3 over k3 = 192 ----
        const uint32_t sP = sb + OFF_P;
        const uint32_t sV = sb + OFF_V + (kt & 1) * 51200;
#pragma unroll 3
        for (int kk = 0; kk < 12; kk++) {
            uint32_t pa0[4], pa1[4], v0[4], v1[4];
            ldsm4(pa0, sP + (uint32_t)(arow * PS_STR + kk * 32 + acol));
            ldsm4(pa1, sP + (uint32_t)((arow + 16) * PS_STR + kk * 32 + acol));
            ldsm4(v0, sV + (uint32_t)(vbrow * VS_STR + kk * 32 + kbcol));
            ldsm4(v1, sV + (uint32_t)((vbrow + 16) * VS_STR + kk * 32 + kbcol));
            mma16816(accO[0][0], pa0, &v0[0]);
            mma16816(accO[0][1], pa0, &v0[2]);
            mma16816(accO[0][2], pa0, &v1[0]);
            mma16816(accO[0][3], pa0, &v1[2]);
            mma16816(accO[1][0], pa1, &v0[0]);
            mma16816(accO[1][1], pa1, &v0[2]);
            mma16816(accO[1][2], pa1, &v1[0]);
            mma16816(accO[1][3], pa1, &v1[2]);
        }
    }

    // ---- one-time row-sum reduction ----
    float* rs = (float*)(asmem + OFF_RS);
#pragma unroll
    for (int mi = 0; mi < 2; mi++)
#pragma unroll
        for (int hf = 0; hf < 2; hf++) {
            float v = psum[mi][hf];
            v += __shfl_xor_sync(0xffffffffu, v, 1);
            v += __shfl_xor_sync(0xffffffffu, v, 2);
            psum[mi][hf] = v;
        }
    __syncthreads();               // last PV done before reusing SMEM region
    if ((lane & 3) == 0) {
#pragma unroll
        for (int mi = 0; mi < 2; mi++)
#pragma unroll
            for (int hf = 0; hf < 2; hf++)
                rs[wn * 64 + wm * 32 + mi * 16 + hf * 8 + (lane >> 2)] = psum[mi][hf];
    }
    __syncthreads();

    // ---- epilogue: normalize, write g_at3 triplets (A-side h,h,l) ----
#pragma unroll
    for (int mi = 0; mi < 2; mi++) {
#pragma unroll
        for (int hf = 0; hf < 2; hf++) {
            const int lrow = wm * 32 + mi * 16 + hf * 8 + (lane >> 2);
            const float lsum = rs[0 * 64 + lrow] + rs[1 * 64 + lrow]
                             + rs[2 * 64 + lrow] + rs[3 * 64 + lrow];
            const float inv = 1.f / lsum;
            const int row = q0 + lrow;
#pragma unroll
            for (int ni = 0; ni < 4; ni++) {
                const int dcol = wn * 32 + ni * 8 + (lane & 3) * 2;
                const float v0 = accO[mi][ni][hf * 2 + 0] * inv;
                const float v1 = accO[mi][ni][hf * 2 + 1] * inv;
                __nv_bfloat16 h0, l0, h1, l1;
                split2(v0, h0, l0); split2(v1, h1, l1);
                uint32_t* dp = (uint32_t*)(g_at3 + (ull)row * K3 + 3 * (h * HD + dcol));
                dp[0] = bfpack(h0, h0);
                dp[1] = bfpack(l0, h1);
                dp[2] = bfpack(h1, l1);
            }
        }
    }
}

// ---------------- launch ----------------
extern "C" void kernel_launch(void* const* d_in, const int* in_sizes, int n_in,
                              void* d_out, int out_size)
{
    const float* x     = (const float*)d_in[0];
    const float* Wq    = (const float*)d_in[1];
    const float* bq    = (const float*)d_in[2];
    const float* Wk    = (const float*)d_in[3];
    const float* bk    = (const float*)d_in[4];
    const float* Wv    = (const float*)d_in[5];
    const float* bv    = (const float*)d_in[6];
    const float* Wo    = (const float*)d_in[7];
    const float* khist = (const float*)d_in[8];
    const float* vhist = (const float*)d_in[9];
    const float* fcos  = (const float*)d_in[10];
    const float* fsin  = (const float*)d_in[11];
    float* out = (float*)d_out;

    cudaFuncSetAttribute(attention_kernel,
                         cudaFuncAttributeMaxDynamicSharedMemorySize, ATT_SMEM);
    cudaFuncSetAttribute(hmma_gemm_kernel,
                         cudaFuncAttributeMaxDynamicSharedMemorySize, GEMM_SMEM);

    conv_x3_kernel<<<QL * HID / 256, 256>>>(x);
    conv_wqkv3_kernel<<<dim3(64, 48), dim3(32, 8)>>>(Wq, Wk, Wv);
    conv_wo3_kernel<<<dim3(48, 48), dim3(32, 8)>>>(Wo);

    hmma_gemm_kernel<<<dim3(16, 16), 256, GEMM_SMEM>>>(0, nullptr, bq, bk, bv);

    rope_q_kernel<<<QL, NH * 64>>>(fcos, fsin);
    build_kv_kernel<<<dim3(KLEN, NKVH), 64>>>(khist, vhist, fcos, fsin);
    vt3_kernel<<<dim3(KLEN / 32, HD / 32, NKVH), dim3(32, 8)>>>();

    attention_kernel<<<dim3(NH, 32), 256, ATT_SMEM>>>();

    hmma_gemm_kernel<<<dim3(12, 16), 256, GEMM_SMEM>>>(1, out, nullptr, nullptr, nullptr);
}

// round 10
// speedup vs baseline: 4.2393x; 1.1297x over previous
#include <cuda_runtime.h>
#include <cuda_bf16.h>
#include <cstdint>

typedef unsigned long long ull;

#define QL    2048
#define HISTL 2048
#define KLEN  4096
#define NH    12
#define NKVH  2
#define HD    128
#define HID   1536
#define GRP   6
#define K3    4608           // 3 * 1536 (hi/lo compensated K extension, GEMM)

// ---------------- scratch (static device globals; no allocation) ----------------
__device__ float g_q[QL * HID];          // Q projection (pre-RoPE, f32)
__device__ float g_kn[QL * NKVH * HD];   // new K projection (pre-RoPE)
__device__ float g_vn[QL * NKVH * HD];   // new V projection
__device__ float g_v[NKVH * KLEN * HD];  // full V (f32, for transpose)

// GEMM triplet operands (proven R7-R9 path)
__device__ __nv_bfloat16 g_x3[QL * K3];
__device__ __nv_bfloat16 g_w3[2048 * K3];
__device__ __nv_bfloat16 g_wo3[HID * K3];
__device__ __nv_bfloat16 g_at3[QL * K3];

// attention plane-split operands (hi / lo separate)
__device__ __nv_bfloat16 g_qh[NH * QL * HD];
__device__ __nv_bfloat16 g_qlo[NH * QL * HD];
__device__ __nv_bfloat16 g_kh[NKVH * KLEN * HD];
__device__ __nv_bfloat16 g_klo[NKVH * KLEN * HD];
__device__ __nv_bfloat16 g_vth[NKVH * HD * KLEN];   // V^T hi: [kv][d][pos]
__device__ __nv_bfloat16 g_vtl[NKVH * HD * KLEN];   // V^T lo

// ---------------- helpers ----------------
__device__ __forceinline__ uint32_t smem_u32(const void* p) {
    uint32_t a;
    asm("{ .reg .u64 t; cvta.to.shared.u64 t, %1; cvt.u32.u64 %0, t; }" : "=r"(a) : "l"(p));
    return a;
}
#define SWZ128(off) ((off) ^ (((off) >> 3) & 0x70))

__device__ __forceinline__ void ldsm4(uint32_t* r, uint32_t addr) {
    asm volatile("ldmatrix.sync.aligned.m8n8.x4.shared.b16 {%0,%1,%2,%3}, [%4];"
        : "=r"(r[0]), "=r"(r[1]), "=r"(r[2]), "=r"(r[3]) : "r"(addr));
}
__device__ __forceinline__ void mma16816(float* d, const uint32_t* a, const uint32_t* b) {
    asm volatile("mma.sync.aligned.m16n8k16.row.col.f32.bf16.bf16.f32 "
        "{%0,%1,%2,%3},{%4,%5,%6,%7},{%8,%9},{%0,%1,%2,%3};"
        : "+f"(d[0]), "+f"(d[1]), "+f"(d[2]), "+f"(d[3])
        : "r"(a[0]), "r"(a[1]), "r"(a[2]), "r"(a[3]), "r"(b[0]), "r"(b[1]));
}
__device__ __forceinline__ void cp_async16(uint32_t saddr, const void* gptr) {
    asm volatile("cp.async.cg.shared.global [%0], [%1], 16;"
        :: "r"(saddr), "l"((size_t)__cvta_generic_to_global(gptr)) : "memory");
}
__device__ __forceinline__ void cp_commit() { asm volatile("cp.async.commit_group;" ::: "memory"); }
__device__ __forceinline__ void cp_wait0()  { asm volatile("cp.async.wait_group 0;" ::: "memory"); }
__device__ __forceinline__ void cp_wait1()  { asm volatile("cp.async.wait_group 1;" ::: "memory"); }

__device__ __forceinline__ void split2(float v, __nv_bfloat16& h, __nv_bfloat16& l) {
    h = __float2bfloat16(v);
    l = __float2bfloat16(v - __bfloat162float(h));
}
__device__ __forceinline__ uint32_t bfpack(__nv_bfloat16 a, __nv_bfloat16 b) {
    return (uint32_t)__bfloat16_as_ushort(a) | ((uint32_t)__bfloat16_as_ushort(b) << 16);
}

// ================= conversion kernels =================
__global__ void conv_x3_kernel(const float* __restrict__ src) {
    const int i = blockIdx.x * blockDim.x + threadIdx.x;
    const int m = i / HID, k = i % HID;
    __nv_bfloat16 h, l;
    split2(src[i], h, l);
    __nv_bfloat16* p = g_x3 + (ull)m * K3 + 3 * k;
    p[0] = h; p[1] = h; p[2] = l;
}

__global__ void conv_wqkv3_kernel(const float* __restrict__ Wq,
                                  const float* __restrict__ Wk,
                                  const float* __restrict__ Wv) {
    __shared__ float t[32][33];
    const int n0 = blockIdx.x * 32, k0 = blockIdx.y * 32;
    const int tx = threadIdx.x, ty = threadIdx.y;
    const float* W; int nb, ld;
    if (n0 < 1536)      { W = Wq; nb = n0;        ld = HID; }
    else if (n0 < 1792) { W = Wk; nb = n0 - 1536; ld = NKVH * HD; }
    else                { W = Wv; nb = n0 - 1792; ld = NKVH * HD; }
    for (int r = ty; r < 32; r += 8)
        t[r][tx] = W[(ull)(k0 + r) * ld + nb + tx];
    __syncthreads();
    for (int r = ty; r < 32; r += 8) {
        __nv_bfloat16 h, l;
        split2(t[tx][r], h, l);
        __nv_bfloat16* p = g_w3 + (ull)(n0 + r) * K3 + 3 * (k0 + tx);
        p[0] = h; p[1] = l; p[2] = h;
    }
}

__global__ void conv_wo3_kernel(const float* __restrict__ Wo) {
    __shared__ float t[32][33];
    const int n0 = blockIdx.x * 32, k0 = blockIdx.y * 32;
    const int tx = threadIdx.x, ty = threadIdx.y;
    for (int r = ty; r < 32; r += 8)
        t[r][tx] = Wo[(ull)(k0 + r) * HID + n0 + tx];
    __syncthreads();
    for (int r = ty; r < 32; r += 8) {
        __nv_bfloat16 h, l;
        split2(t[tx][r], h, l);
        __nv_bfloat16* p = g_wo3 + (ull)(n0 + r) * K3 + 3 * (k0 + tx);
        p[0] = h; p[1] = l; p[2] = h;
    }
}

// ================= HMMA GEMM (proven, 3-stage cp.async) =================
#define CHK     64
#define NCHUNK  (K3 / CHK)          // 72
#define TILE_B  16384
#define NBUF    3
#define GEMM_SMEM (NBUF * 2 * TILE_B)

__global__ __launch_bounds__(256, 2) void hmma_gemm_kernel(
    int mode, float* __restrict__ outp,
    const float* __restrict__ bq, const float* __restrict__ bk, const float* __restrict__ bv)
{
    extern __shared__ __align__(1024) char dynsm[];
    const uint32_t sbase = smem_u32(dynsm);
    const int tid  = threadIdx.x;
    const int lane = tid & 31;
    const int wid  = tid >> 5;
    const int wm   = wid >> 2;
    const int wn   = wid & 3;
    const int m0   = blockIdx.y * 128;
    const int n0   = blockIdx.x * 128;

    const __nv_bfloat16* __restrict__ A3 = (mode == 0) ? g_x3 : g_at3;
    const __nv_bfloat16* __restrict__ B3 = (mode == 0) ? g_w3 : g_wo3;

    float d[4][4][4];
#pragma unroll
    for (int mi = 0; mi < 4; mi++)
#pragma unroll
        for (int ni = 0; ni < 4; ni++)
#pragma unroll
            for (int r = 0; r < 4; r++) d[mi][ni][r] = 0.f;

    const int lr = tid >> 3;
    const int lg = tid & 7;

#pragma unroll
    for (int pc = 0; pc < 2; pc++) {
        const uint32_t sA = sbase + pc * (2u * TILE_B), sB = sA + TILE_B;
        const int k0 = pc * CHK;
#pragma unroll
        for (int it = 0; it < 4; it++) {
            const int r = lr + it * 32;
            const uint32_t so = SWZ128((uint32_t)(r * 128 + lg * 16));
            cp_async16(sA + so, A3 + (ull)(m0 + r) * K3 + k0 + lg * 8);
            cp_async16(sB + so, B3 + (ull)(n0 + r) * K3 + k0 + lg * 8);
        }
        cp_commit();
    }

    const int arow = wm * 64 + (lane & 15);
    const int acol = (lane & 16) ? 16 : 0;
    const int brow = wn * 32 + (lane & 7) + ((lane & 16) ? 8 : 0);
    const int bcol = (lane & 8) ? 16 : 0;

    int ldbuf = 2;
    for (int c = 0; c < NCHUNK; c++) {
        cp_wait1();
        __syncthreads();
        if (c + 2 < NCHUNK) {
            const uint32_t sA = sbase + (uint32_t)ldbuf * (2u * TILE_B), sB = sA + TILE_B;
            const int k0 = (c + 2) * CHK;
#pragma unroll
            for (int it = 0; it < 4; it++) {
                const int r = lr + it * 32;
                const uint32_t so = SWZ128((uint32_t)(r * 128 + lg * 16));
                cp_async16(sA + so, A3 + (ull)(m0 + r) * K3 + k0 + lg * 8);
                cp_async16(sB + so, B3 + (ull)(n0 + r) * K3 + k0 + lg * 8);
            }
            cp_commit();
            if (++ldbuf == NBUF) ldbuf = 0;
        }
        const uint32_t cb = (uint32_t)(c % NBUF) * (2u * TILE_B);
        const uint32_t sA = sbase + cb, sB = sbase + cb + TILE_B;
#pragma unroll
        for (int kk = 0; kk < 4; kk++) {
            uint32_t a[4][4], bb[4][2];
#pragma unroll
            for (int mi = 0; mi < 4; mi++)
                ldsm4(a[mi], sA + SWZ128((uint32_t)((arow + mi * 16) * 128 + kk * 32 + acol)));
            {
                uint32_t t4[4];
                ldsm4(t4, sB + SWZ128((uint32_t)(brow * 128 + kk * 32 + bcol)));
                bb[0][0] = t4[0]; bb[0][1] = t4[1]; bb[1][0] = t4[2]; bb[1][1] = t4[3];
                ldsm4(t4, sB + SWZ128((uint32_t)((brow + 16) * 128 + kk * 32 + bcol)));
                bb[2][0] = t4[0]; bb[2][1] = t4[1]; bb[3][0] = t4[2]; bb[3][1] = t4[3];
            }
#pragma unroll
            for (int mi = 0; mi < 4; mi++)
#pragma unroll
                for (int ni = 0; ni < 4; ni++)
                    mma16816(d[mi][ni], a[mi], bb[ni]);
        }
        __syncthreads();
    }

    float* dst; int ldc; const float* bias; int coff;
    if (mode == 1)        { dst = outp; ldc = HID;       bias = nullptr;          coff = n0; }
    else if (n0 < 1536)   { dst = g_q;  ldc = HID;       bias = bq + n0;          coff = n0; }
    else if (n0 < 1792)   { dst = g_kn; ldc = NKVH * HD; bias = bk + (n0 - 1536); coff = n0 - 1536; }
    else                  { dst = g_vn; ldc = NKVH * HD; bias = bv + (n0 - 1792); coff = n0 - 1792; }

#pragma unroll
    for (int mi = 0; mi < 4; mi++) {
        const int r0 = m0 + wm * 64 + mi * 16 + (lane >> 2);
#pragma unroll
        for (int ni = 0; ni < 4; ni++) {
            const int cl = wn * 32 + ni * 8 + (lane & 3) * 2;
            float b0 = 0.f, b1 = 0.f;
            if (bias) { b0 = bias[cl]; b1 = bias[cl + 1]; }
            float2 v0 = { d[mi][ni][0] + b0, d[mi][ni][1] + b1 };
            float2 v1 = { d[mi][ni][2] + b0, d[mi][ni][3] + b1 };
            *(float2*)(dst + (ull)r0 * ldc + coff + cl)       = v0;
            *(float2*)(dst + (ull)(r0 + 8) * ldc + coff + cl) = v1;
        }
    }
}

// ---------------- RoPE on Q -> Qh/Ql planes ----------------
__global__ void rope_q_kernel(const float* __restrict__ fcos, const float* __restrict__ fsin)
{
    const int t = blockIdx.x;
    const int h = threadIdx.x >> 6;
    const int i = threadIdx.x & 63;
    const float* q = g_q + (ull)t * HID + h * HD;
    const float c = fcos[t * 64 + i];
    const float s = fsin[t * 64 + i];
    const float x1 = q[i];
    const float x2 = q[i + 64];
    const float r1 = x1 * c - x2 * s;
    const float r2 = x1 * s + x2 * c;
    __nv_bfloat16 h1, l1, h2, l2;
    split2(r1, h1, l1); split2(r2, h2, l2);
    const ull base = ((ull)h * QL + t) * HD;
    g_qh[base + i] = h1;       g_qlo[base + i] = l1;
    g_qh[base + i + 64] = h2;  g_qlo[base + i + 64] = l2;
}

// ---------------- build full K planes + V (f32) ----------------
__global__ void build_kv_kernel(
    const float* __restrict__ k_hist, const float* __restrict__ v_hist,
    const float* __restrict__ fcos, const float* __restrict__ fsin)
{
    const int pos = blockIdx.x;
    const int kv = blockIdx.y;
    const int i = threadIdx.x;
    float* vd = g_v + ((ull)(kv * KLEN + pos)) * HD;
    float k1, k2;
    if (pos < HISTL) {
        const float* ks = k_hist + ((ull)pos * NKVH + kv) * HD;
        const float* vs = v_hist + ((ull)pos * NKVH + kv) * HD;
        k1 = ks[i]; k2 = ks[i + 64];
        vd[i] = vs[i]; vd[i + 64] = vs[i + 64];
    } else {
        const int t = pos - HISTL;
        const float* ks = g_kn + (ull)t * (NKVH * HD) + kv * HD;
        const float* vs = g_vn + (ull)t * (NKVH * HD) + kv * HD;
        const float c = fcos[t * 64 + i];
        const float s = fsin[t * 64 + i];
        const float x1 = ks[i];
        const float x2 = ks[i + 64];
        k1 = x1 * c - x2 * s;
        k2 = x1 * s + x2 * c;
        vd[i] = vs[i]; vd[i + 64] = vs[i + 64];
    }
    __nv_bfloat16 h1, l1, h2, l2;
    split2(k1, h1, l1); split2(k2, h2, l2);
    const ull base = ((ull)(kv * KLEN + pos)) * HD;
    g_kh[base + i] = h1;       g_klo[base + i] = l1;
    g_kh[base + i + 64] = h2;  g_klo[base + i + 64] = l2;
}

// ---------------- transpose V -> V^T planes ----------------
__global__ void vt_kernel() {
    __shared__ float t[32][33];
    const int pos0 = blockIdx.x * 32, d0 = blockIdx.y * 32, kv = blockIdx.z;
    const int tx = threadIdx.x, ty = threadIdx.y;
    for (int r = ty; r < 32; r += 8)
        t[r][tx] = g_v[((ull)(kv * KLEN + pos0 + r)) * HD + d0 + tx];
    __syncthreads();
    for (int r = ty; r < 32; r += 8) {
        __nv_bfloat16 h, l;
        split2(t[tx][r], h, l);
        const ull o = ((ull)(kv * HD + d0 + r)) * KLEN + pos0 + tx;
        g_vth[o] = h; g_vtl[o] = l;
    }
}

// ================= HMMA flash attention (plane-split, fragment-held) =================
#define QSTR 272            // Qh/Ql/Kh/Kl row stride (128 d x 2B + 16 pad)
#define VSTR 144            // Vh/Vl/Ph/Pl row stride (64 keys x 2B + 16 pad)
#define OFF_QH 0
#define OFF_QL 17408
#define OFF_KH 34816
#define OFF_KL 52224
#define OFF_V  69632        // per buf: Vh (18432) then Vl (18432); 2 bufs
#define VBUF_B 36864
#define OFF_PH 143360
#define OFF_PL 152576
#define OFF_RS 161792
#define ATT_SMEM 162816

__global__ __launch_bounds__(256, 1) void attention_kernel()
{
    extern __shared__ __align__(1024) char asmem[];
    const uint32_t sb = smem_u32(asmem);
    const int h  = blockIdx.x;
    const int qb = 31 - blockIdx.y;
    const int kvh = h / GRP;
    const int q0 = qb * 64;
    const int tid = threadIdx.x;
    const int lane = tid & 31;
    const int wid = tid >> 5;
    const int wm = wid >> 2;      // 0..1
    const int wn = wid & 3;       // 0..3
    const int n_tiles = qb + 33;

    const __nv_bfloat16* Qgh = g_qh  + ((ull)h * QL + q0) * HD;
    const __nv_bfloat16* Qgl = g_qlo + ((ull)h * QL + q0) * HD;
    const __nv_bfloat16* Kgh = g_kh  + ((ull)kvh * KLEN) * HD;
    const __nv_bfloat16* Kgl = g_klo + ((ull)kvh * KLEN) * HD;
    const __nv_bfloat16* Vgh = g_vth + ((ull)kvh * HD) * KLEN;
    const __nv_bfloat16* Vgl = g_vtl + ((ull)kvh * HD) * KLEN;

    // ---- prologue: Q planes + K[0] planes + V[0] planes ----
    for (int u = tid; u < 64 * 16; u += 256) {
        const int r = u >> 4, c = u & 15;
        cp_async16(sb + OFF_QH + r * QSTR + c * 16, Qgh + (ull)r * HD + c * 8);
        cp_async16(sb + OFF_QL + r * QSTR + c * 16, Qgl + (ull)r * HD + c * 8);
        cp_async16(sb + OFF_KH + r * QSTR + c * 16, Kgh + (ull)r * HD + c * 8);
        cp_async16(sb + OFF_KL + r * QSTR + c * 16, Kgl + (ull)r * HD + c * 8);
    }
    for (int u = tid; u < 128 * 8; u += 256) {
        const int r = u >> 3, c = u & 7;
        cp_async16(sb + OFF_V + r * VSTR + c * 16,         Vgh + (ull)r * KLEN + c * 8);
        cp_async16(sb + OFF_V + 18432 + r * VSTR + c * 16, Vgl + (ull)r * KLEN + c * 8);
    }
    cp_commit();

    float accO[2][4][4];
    float psum[2][2];
#pragma unroll
    for (int mi = 0; mi < 2; mi++) {
#pragma unroll
        for (int hf = 0; hf < 2; hf++) psum[mi][hf] = 0.f;
#pragma unroll
        for (int ni = 0; ni < 4; ni++)
#pragma unroll
            for (int r = 0; r < 4; r++) accO[mi][ni][r] = 0.f;
    }

    const int arow = wm * 32 + (lane & 15);
    const int acol = (lane & 16) ? 16 : 0;
    const int qbrow = wn * 16 + (lane & 7) + ((lane & 16) ? 8 : 0);
    const int vbrow = wn * 32 + (lane & 7) + ((lane & 16) ? 8 : 0);
    const int kbcol = (lane & 8) ? 16 : 0;

    for (int kt = 0; kt < n_tiles; kt++) {
        cp_wait0();
        __syncthreads();           // tile data ready; prev PV done

        // ==== S = Q K^T, 3 passes with held fragments ====
        float S[2][2][4];
#pragma unroll
        for (int mi = 0; mi < 2; mi++)
#pragma unroll
            for (int nf = 0; nf < 2; nf++)
#pragma unroll
                for (int r = 0; r < 4; r++) S[mi][nf][r] = 0.f;

        uint32_t qf[8][2][4];      // Qh fragments, held
        uint32_t kf[8][4];         // Kh fragments, held
        // pass 1: Qh * Kh  (load + hold)
#pragma unroll
        for (int kk = 0; kk < 8; kk++) {
            ldsm4(qf[kk][0], sb + OFF_QH + (uint32_t)(arow * QSTR + kk * 32 + acol));
            ldsm4(qf[kk][1], sb + OFF_QH + (uint32_t)((arow + 16) * QSTR + kk * 32 + acol));
            ldsm4(kf[kk],    sb + OFF_KH + (uint32_t)(qbrow * QSTR + kk * 32 + kbcol));
            mma16816(S[0][0], qf[kk][0], &kf[kk][0]);
            mma16816(S[0][1], qf[kk][0], &kf[kk][2]);
            mma16816(S[1][0], qf[kk][1], &kf[kk][0]);
            mma16816(S[1][1], qf[kk][1], &kf[kk][2]);
        }
        // pass 2: Qh * Kl  (Qh held, Kl streamed)
#pragma unroll
        for (int kk = 0; kk < 8; kk++) {
            uint32_t t4[4];
            ldsm4(t4, sb + OFF_KL + (uint32_t)(qbrow * QSTR + kk * 32 + kbcol));
            mma16816(S[0][0], qf[kk][0], &t4[0]);
            mma16816(S[0][1], qf[kk][0], &t4[2]);
            mma16816(S[1][0], qf[kk][1], &t4[0]);
            mma16816(S[1][1], qf[kk][1], &t4[2]);
        }
        // pass 3: Ql * Kh  (Kh held, Ql streamed)
#pragma unroll
        for (int kk = 0; kk < 8; kk++) {
            uint32_t t0[4], t1[4];
            ldsm4(t0, sb + OFF_QL + (uint32_t)(arow * QSTR + kk * 32 + acol));
            ldsm4(t1, sb + OFF_QL + (uint32_t)((arow + 16) * QSTR + kk * 32 + acol));
            mma16816(S[0][0], t0, &kf[kk][0]);
            mma16816(S[0][1], t0, &kf[kk][2]);
            mma16816(S[1][0], t1, &kf[kk][0]);
            mma16816(S[1][1], t1, &kf[kk][2]);
        }
        __syncthreads();           // all QK ldsm done -> K SMEM reusable

        // ---- prefetch next tile's K planes (+V alt buffer planes) ----
        if (kt + 1 < n_tiles) {
            const int kb2 = (kt + 1) * 64;
            for (int u = tid; u < 64 * 16; u += 256) {
                const int r = u >> 4, c = u & 15;
                cp_async16(sb + OFF_KH + r * QSTR + c * 16, Kgh + (ull)(kb2 + r) * HD + c * 8);
                cp_async16(sb + OFF_KL + r * QSTR + c * 16, Kgl + (ull)(kb2 + r) * HD + c * 8);
            }
            const uint32_t vbuf = sb + OFF_V + ((kt + 1) & 1) * VBUF_B;
            for (int u = tid; u < 128 * 8; u += 256) {
                const int r = u >> 3, c = u & 7;
                cp_async16(vbuf + r * VSTR + c * 16,         Vgh + (ull)r * KLEN + kb2 + c * 8);
                cp_async16(vbuf + 18432 + r * VSTR + c * 16, Vgl + (ull)r * KLEN + kb2 + c * 8);
            }
            cp_commit();
        }

        // ---- scale + mask + exp + write Ph/Pl planes + partial sums ----
        const int kb = kt * 64;
        const bool maskt = (kt == qb + 32);
#pragma unroll
        for (int mi = 0; mi < 2; mi++)
#pragma unroll
            for (int nf = 0; nf < 2; nf++)
#pragma unroll
                for (int hf = 0; hf < 2; hf++) {
                    float s0 = S[mi][nf][hf * 2 + 0] * 0.08838834764831845f;
                    float s1 = S[mi][nf][hf * 2 + 1] * 0.08838834764831845f;
                    if (maskt) {
                        const int qg = q0 + wm * 32 + mi * 16 + (lane >> 2) + hf * 8;
                        const int kg = kb + wn * 16 + nf * 8 + (lane & 3) * 2;
                        if (kg > qg + HISTL)     s0 = -1e30f;
                        if (kg + 1 > qg + HISTL) s1 = -1e30f;
                    }
                    const float p0 = __expf(s0);
                    const float p1 = __expf(s1);
                    psum[mi][hf] += p0 + p1;
                    __nv_bfloat16 h0, l0, h1, l1;
                    split2(p0, h0, l0); split2(p1, h1, l1);
                    const int row = wm * 32 + mi * 16 + hf * 8 + (lane >> 2);
                    const int c2 = wn * 16 + nf * 8 + (lane & 3) * 2;
                    *(uint32_t*)(asmem + OFF_PH + row * VSTR + 2 * c2) = bfpack(h0, h1);
                    *(uint32_t*)(asmem + OFF_PL + row * VSTR + 2 * c2) = bfpack(l0, l1);
                }
        __syncthreads();           // P planes ready

        // ==== O += P @ V^T, 3 passes with held fragments ====
        const uint32_t sPH = sb + OFF_PH;
        const uint32_t sPL = sb + OFF_PL;
        const uint32_t sVH = sb + OFF_V + (kt & 1) * VBUF_B;
        const uint32_t sVL = sVH + 18432;

        uint32_t pf[4][2][4];      // Ph fragments, held
        uint32_t vf[4][2][4];      // Vh fragments, held
        // pass 1: Ph * Vh
#pragma unroll
        for (int kk = 0; kk < 4; kk++) {
            ldsm4(pf[kk][0], sPH + (uint32_t)(arow * VSTR + kk * 32 + acol));
            ldsm4(pf[kk][1], sPH + (uint32_t)((arow + 16) * VSTR + kk * 32 + acol));
            ldsm4(vf[kk][0], sVH + (uint32_t)(vbrow * VSTR + kk * 32 + kbcol));
            ldsm4(vf[kk][1], sVH + (uint32_t)((vbrow + 16) * VSTR + kk * 32 + kbcol));
            mma16816(accO[0][0], pf[kk][0], &vf[kk][0][0]);
            mma16816(accO[0][1], pf[kk][0], &vf[kk][0][2]);
            mma16816(accO[0][2], pf[kk][0], &vf[kk][1][0]);
            mma16816(accO[0][3], pf[kk][0], &vf[kk][1][2]);
            mma16816(accO[1][0], pf[kk][1], &vf[kk][0][0]);
            mma16816(accO[1][1], pf[kk][1], &vf[kk][0][2]);
            mma16816(accO[1][2], pf[kk][1], &vf[kk][1][0]);
            mma16816(accO[1][3], pf[kk][1], &vf[kk][1][2]);
        }
        // pass 2: Ph * Vl  (Ph held, Vl streamed)
#pragma unroll
        for (int kk = 0; kk < 4; kk++) {
            uint32_t t0[4], t1[4];
            ldsm4(t0, sVL + (uint32_t)(vbrow * VSTR + kk * 32 + kbcol));
            ldsm4(t1, sVL + (uint32_t)((vbrow + 16) * VSTR + kk * 32 + kbcol));
            mma16816(accO[0][0], pf[kk][0], &t0[0]);
            mma16816(accO[0][1], pf[kk][0], &t0[2]);
            mma16816(accO[0][2], pf[kk][0], &t1[0]);
            mma16816(accO[0][3], pf[kk][0], &t1[2]);
            mma16816(accO[1][0], pf[kk][1], &t0[0]);
            mma16816(accO[1][1], pf[kk][1], &t0[2]);
            mma16816(accO[1][2], pf[kk][1], &t1[0]);
            mma16816(accO[1][3], pf[kk][1], &t1[2]);
        }
        // pass 3: Pl * Vh  (Vh held, Pl streamed)
#pragma unroll
        for (int kk = 0; kk < 4; kk++) {
            uint32_t p0[4], p1[4];
            ldsm4(p0, sPL + (uint32_t)(arow * VSTR + kk * 32 + acol));
            ldsm4(p1, sPL + (uint32_t)((arow + 16) * VSTR + kk * 32 + acol));
            mma16816(accO[0][0], p0, &vf[kk][0][0]);
            mma16816(accO[0][1], p0, &vf[kk][0][2]);
            mma16816(accO[0][2], p0, &vf[kk][1][0]);
            mma16816(accO[0][3], p0, &vf[kk][1][2]);
            mma16816(accO[1][0], p1, &vf[kk][0][0]);
            mma16816(accO[1][1], p1, &vf[kk][0][2]);
            mma16816(accO[1][2], p1, &vf[kk][1][0]);
            mma16816(accO[1][3], p1, &vf[kk][1][2]);
        }
    }

    // ---- one-time row-sum reduction ----
    float* rs = (float*)(asmem + OFF_RS);
#pragma unroll
    for (int mi = 0; mi < 2; mi++)
#pragma unroll
        for (int hf = 0; hf < 2; hf++) {
            float v = psum[mi][hf];
            v += __shfl_xor_sync(0xffffffffu, v, 1);
            v += __shfl_xor_sync(0xffffffffu, v, 2);
            psum[mi][hf] = v;
        }
    __syncthreads();
    if ((lane & 3) == 0) {
#pragma unroll
        for (int mi = 0; mi < 2; mi++)
#pragma unroll
            for (int hf = 0; hf < 2; hf++)
                rs[wn * 64 + wm * 32 + mi * 16 + hf * 8 + (lane >> 2)] = psum[mi][hf];
    }
    __syncthreads();

    // ---- epilogue: normalize, write g_at3 triplets (A-side h,h,l) ----
#pragma unroll
    for (int mi = 0; mi < 2; mi++) {
#pragma unroll
        for (int hf = 0; hf < 2; hf++) {
            const int lrow = wm * 32 + mi * 16 + hf * 8 + (lane >> 2);
            const float lsum = rs[0 * 64 + lrow] + rs[1 * 64 + lrow]
                             + rs[2 * 64 + lrow] + rs[3 * 64 + lrow];
            const float inv = 1.f / lsum;
            const int row = q0 + lrow;
#pragma unroll
            for (int ni = 0; ni < 4; ni++) {
                const int dcol = wn * 32 + ni * 8 + (lane & 3) * 2;
                const float v0 = accO[mi][ni][hf * 2 + 0] * inv;
                const float v1 = accO[mi][ni][hf * 2 + 1] * inv;
                __nv_bfloat16 h0, l0, h1, l1;
                split2(v0, h0, l0); split2(v1, h1, l1);
                uint32_t* dp = (uint32_t*)(g_at3 + (ull)row * K3 + 3 * (h * HD + dcol));
                dp[0] = bfpack(h0, h0);
                dp[1] = bfpack(l0, h1);
                dp[2] = bfpack(h1, l1);
            }
        }
    }
}

// ---------------- launch ----------------
extern "C" void kernel_launch(void* const* d_in, const int* in_sizes, int n_in,
                              void* d_out, int out_size)
{
    const float* x     = (const float*)d_in[0];
    const float* Wq    = (const float*)d_in[1];
    const float* bq    = (const float*)d_in[2];
    const float* Wk    = (const float*)d_in[3];
    const float* bk    = (const float*)d_in[4];
    const float* Wv    = (const float*)d_in[5];
    const float* bv    = (const float*)d_in[6];
    const float* Wo    = (const float*)d_in[7];
    const float* khist = (const float*)d_in[8];
    const float* vhist = (const float*)d_in[9];
    const float* fcos  = (const float*)d_in[10];
    const float* fsin  = (const float*)d_in[11];
    float* out = (float*)d_out;

    cudaFuncSetAttribute(attention_kernel,
                         cudaFuncAttributeMaxDynamicSharedMemorySize, ATT_SMEM);
    cudaFuncSetAttribute(hmma_gemm_kernel,
                         cudaFuncAttributeMaxDynamicSharedMemorySize, GEMM_SMEM);

    conv_x3_kernel<<<QL * HID / 256, 256>>>(x);
    conv_wqkv3_kernel<<<dim3(64, 48), dim3(32, 8)>>>(Wq, Wk, Wv);
    conv_wo3_kernel<<<dim3(48, 48), dim3(32, 8)>>>(Wo);

    hmma_gemm_kernel<<<dim3(16, 16), 256, GEMM_SMEM>>>(0, nullptr, bq, bk, bv);

    rope_q_kernel<<<QL, NH * 64>>>(fcos, fsin);
    build_kv_kernel<<<dim3(KLEN, NKVH), 64>>>(khist, vhist, fcos, fsin);
    vt_kernel<<<dim3(KLEN / 32, HD / 32, NKVH), dim3(32, 8)>>>();

    attention_kernel<<<dim3(NH, 32), 256, ATT_SMEM>>>();

    hmma_gemm_kernel<<<dim3(12, 16), 256, GEMM_SMEM>>>(1, out, nullptr, nullptr, nullptr);
}

// round 11
// speedup vs baseline: 4.4252x; 1.0439x over previous
#include <cuda_runtime.h>
#include <cuda_bf16.h>
#include <cstdint>

typedef unsigned long long ull;

#define QL    2048
#define HISTL 2048
#define KLEN  4096
#define NH    12
#define NKVH  2
#define HD    128
#define HID   1536
#define GRP   6
#define K3    4608           // 3 * 1536 (hi/lo compensated K extension, GEMM)

// ---------------- scratch (static device globals; no allocation) ----------------
__device__ float g_q[QL * HID];          // Q projection (pre-RoPE, f32)
__device__ float g_kn[QL * NKVH * HD];   // new K projection (pre-RoPE)
__device__ float g_vn[QL * NKVH * HD];   // new V projection
__device__ float g_v[NKVH * KLEN * HD];  // full V (f32, for transpose)

// GEMM triplet operands (proven R7-R9 path)
__device__ __nv_bfloat16 g_x3[QL * K3];
__device__ __nv_bfloat16 g_w3[2048 * K3];
__device__ __nv_bfloat16 g_wo3[HID * K3];
__device__ __nv_bfloat16 g_at3[QL * K3];

// attention plane-split operands (hi / lo separate)
__device__ __nv_bfloat16 g_qh[NH * QL * HD];
__device__ __nv_bfloat16 g_qlo[NH * QL * HD];
__device__ __nv_bfloat16 g_kh[NKVH * KLEN * HD];
__device__ __nv_bfloat16 g_klo[NKVH * KLEN * HD];
__device__ __nv_bfloat16 g_vth[NKVH * HD * KLEN];   // V^T hi: [kv][d][pos]
__device__ __nv_bfloat16 g_vtl[NKVH * HD * KLEN];   // V^T lo

// ---------------- helpers ----------------
__device__ __forceinline__ uint32_t smem_u32(const void* p) {
    uint32_t a;
    asm("{ .reg .u64 t; cvta.to.shared.u64 t, %1; cvt.u32.u64 %0, t; }" : "=r"(a) : "l"(p));
    return a;
}
#define SWZ128(off) ((off) ^ (((off) >> 3) & 0x70))

__device__ __forceinline__ void ldsm4(uint32_t* r, uint32_t addr) {
    asm volatile("ldmatrix.sync.aligned.m8n8.x4.shared.b16 {%0,%1,%2,%3}, [%4];"
        : "=r"(r[0]), "=r"(r[1]), "=r"(r[2]), "=r"(r[3]) : "r"(addr));
}
__device__ __forceinline__ void mma16816(float* d, const uint32_t* a, const uint32_t* b) {
    asm volatile("mma.sync.aligned.m16n8k16.row.col.f32.bf16.bf16.f32 "
        "{%0,%1,%2,%3},{%4,%5,%6,%7},{%8,%9},{%0,%1,%2,%3};"
        : "+f"(d[0]), "+f"(d[1]), "+f"(d[2]), "+f"(d[3])
        : "r"(a[0]), "r"(a[1]), "r"(a[2]), "r"(a[3]), "r"(b[0]), "r"(b[1]));
}
__device__ __forceinline__ void cp_async16(uint32_t saddr, const void* gptr) {
    asm volatile("cp.async.cg.shared.global [%0], [%1], 16;"
        :: "r"(saddr), "l"((size_t)__cvta_generic_to_global(gptr)) : "memory");
}
__device__ __forceinline__ void cp_commit() { asm volatile("cp.async.commit_group;" ::: "memory"); }
__device__ __forceinline__ void cp_wait0()  { asm volatile("cp.async.wait_group 0;" ::: "memory"); }
__device__ __forceinline__ void cp_wait1()  { asm volatile("cp.async.wait_group 1;" ::: "memory"); }

__device__ __forceinline__ void split2(float v, __nv_bfloat16& h, __nv_bfloat16& l) {
    h = __float2bfloat16(v);
    l = __float2bfloat16(v - __bfloat162float(h));
}
__device__ __forceinline__ uint32_t bfpack(__nv_bfloat16 a, __nv_bfloat16 b) {
    return (uint32_t)__bfloat16_as_ushort(a) | ((uint32_t)__bfloat16_as_ushort(b) << 16);
}

// ================= conversion kernels =================
__global__ void conv_x3_kernel(const float* __restrict__ src) {
    const int i = blockIdx.x * blockDim.x + threadIdx.x;
    const int m = i / HID, k = i % HID;
    __nv_bfloat16 h, l;
    split2(src[i], h, l);
    __nv_bfloat16* p = g_x3 + (ull)m * K3 + 3 * k;
    p[0] = h; p[1] = h; p[2] = l;
}

__global__ void conv_wqkv3_kernel(const float* __restrict__ Wq,
                                  const float* __restrict__ Wk,
                                  const float* __restrict__ Wv) {
    __shared__ float t[32][33];
    const int n0 = blockIdx.x * 32, k0 = blockIdx.y * 32;
    const int tx = threadIdx.x, ty = threadIdx.y;
    const float* W; int nb, ld;
    if (n0 < 1536)      { W = Wq; nb = n0;        ld = HID; }
    else if (n0 < 1792) { W = Wk; nb = n0 - 1536; ld = NKVH * HD; }
    else                { W = Wv; nb = n0 - 1792; ld = NKVH * HD; }
    for (int r = ty; r < 32; r += 8)
        t[r][tx] = W[(ull)(k0 + r) * ld + nb + tx];
    __syncthreads();
    for (int r = ty; r < 32; r += 8) {
        __nv_bfloat16 h, l;
        split2(t[tx][r], h, l);
        __nv_bfloat16* p = g_w3 + (ull)(n0 + r) * K3 + 3 * (k0 + tx);
        p[0] = h; p[1] = l; p[2] = h;
    }
}

__global__ void conv_wo3_kernel(const float* __restrict__ Wo) {
    __shared__ float t[32][33];
    const int n0 = blockIdx.x * 32, k0 = blockIdx.y * 32;
    const int tx = threadIdx.x, ty = threadIdx.y;
    for (int r = ty; r < 32; r += 8)
        t[r][tx] = Wo[(ull)(k0 + r) * HID + n0 + tx];
    __syncthreads();
    for (int r = ty; r < 32; r += 8) {
        __nv_bfloat16 h, l;
        split2(t[tx][r], h, l);
        __nv_bfloat16* p = g_wo3 + (ull)(n0 + r) * K3 + 3 * (k0 + tx);
        p[0] = h; p[1] = l; p[2] = h;
    }
}

// ================= HMMA GEMM (proven, 3-stage cp.async) =================
#define CHK     64
#define NCHUNK  (K3 / CHK)          // 72
#define TILE_B  16384
#define NBUF    3
#define GEMM_SMEM (NBUF * 2 * TILE_B)

__global__ __launch_bounds__(256, 2) void hmma_gemm_kernel(
    int mode, float* __restrict__ outp,
    const float* __restrict__ bq, const float* __restrict__ bk, const float* __restrict__ bv)
{
    extern __shared__ __align__(1024) char dynsm[];
    const uint32_t sbase = smem_u32(dynsm);
    const int tid  = threadIdx.x;
    const int lane = tid & 31;
    const int wid  = tid >> 5;
    const int wm   = wid >> 2;
    const int wn   = wid & 3;
    const int m0   = blockIdx.y * 128;
    const int n0   = blockIdx.x * 128;

    const __nv_bfloat16* __restrict__ A3 = (mode == 0) ? g_x3 : g_at3;
    const __nv_bfloat16* __restrict__ B3 = (mode == 0) ? g_w3 : g_wo3;

    float d[4][4][4];
#pragma unroll
    for (int mi = 0; mi < 4; mi++)
#pragma unroll
        for (int ni = 0; ni < 4; ni++)
#pragma unroll
            for (int r = 0; r < 4; r++) d[mi][ni][r] = 0.f;

    const int lr = tid >> 3;
    const int lg = tid & 7;

#pragma unroll
    for (int pc = 0; pc < 2; pc++) {
        const uint32_t sA = sbase + pc * (2u * TILE_B), sB = sA + TILE_B;
        const int k0 = pc * CHK;
#pragma unroll
        for (int it = 0; it < 4; it++) {
            const int r = lr + it * 32;
            const uint32_t so = SWZ128((uint32_t)(r * 128 + lg * 16));
            cp_async16(sA + so, A3 + (ull)(m0 + r) * K3 + k0 + lg * 8);
            cp_async16(sB + so, B3 + (ull)(n0 + r) * K3 + k0 + lg * 8);
        }
        cp_commit();
    }

    const int arow = wm * 64 + (lane & 15);
    const int acol = (lane & 16) ? 16 : 0;
    const int brow = wn * 32 + (lane & 7) + ((lane & 16) ? 8 : 0);
    const int bcol = (lane & 8) ? 16 : 0;

    int ldbuf = 2;
    for (int c = 0; c < NCHUNK; c++) {
        cp_wait1();
        __syncthreads();
        if (c + 2 < NCHUNK) {
            const uint32_t sA = sbase + (uint32_t)ldbuf * (2u * TILE_B), sB = sA + TILE_B;
            const int k0 = (c + 2) * CHK;
#pragma unroll
            for (int it = 0; it < 4; it++) {
                const int r = lr + it * 32;
                const uint32_t so = SWZ128((uint32_t)(r * 128 + lg * 16));
                cp_async16(sA + so, A3 + (ull)(m0 + r) * K3 + k0 + lg * 8);
                cp_async16(sB + so, B3 + (ull)(n0 + r) * K3 + k0 + lg * 8);
            }
            cp_commit();
            if (++ldbuf == NBUF) ldbuf = 0;
        }
        const uint32_t cb = (uint32_t)(c % NBUF) * (2u * TILE_B);
        const uint32_t sA = sbase + cb, sB = sbase + cb + TILE_B;
#pragma unroll
        for (int kk = 0; kk < 4; kk++) {
            uint32_t a[4][4], bb[4][2];
#pragma unroll
            for (int mi = 0; mi < 4; mi++)
                ldsm4(a[mi], sA + SWZ128((uint32_t)((arow + mi * 16) * 128 + kk * 32 + acol)));
            {
                uint32_t t4[4];
                ldsm4(t4, sB + SWZ128((uint32_t)(brow * 128 + kk * 32 + bcol)));
                bb[0][0] = t4[0]; bb[0][1] = t4[1]; bb[1][0] = t4[2]; bb[1][1] = t4[3];
                ldsm4(t4, sB + SWZ128((uint32_t)((brow + 16) * 128 + kk * 32 + bcol)));
                bb[2][0] = t4[0]; bb[2][1] = t4[1]; bb[3][0] = t4[2]; bb[3][1] = t4[3];
            }
#pragma unroll
            for (int mi = 0; mi < 4; mi++)
#pragma unroll
                for (int ni = 0; ni < 4; ni++)
                    mma16816(d[mi][ni], a[mi], bb[ni]);
        }
        __syncthreads();
    }

    float* dst; int ldc; const float* bias; int coff;
    if (mode == 1)        { dst = outp; ldc = HID;       bias = nullptr;          coff = n0; }
    else if (n0 < 1536)   { dst = g_q;  ldc = HID;       bias = bq + n0;          coff = n0; }
    else if (n0 < 1792)   { dst = g_kn; ldc = NKVH * HD; bias = bk + (n0 - 1536); coff = n0 - 1536; }
    else                  { dst = g_vn; ldc = NKVH * HD; bias = bv + (n0 - 1792); coff = n0 - 1792; }

#pragma unroll
    for (int mi = 0; mi < 4; mi++) {
        const int r0 = m0 + wm * 64 + mi * 16 + (lane >> 2);
#pragma unroll
        for (int ni = 0; ni < 4; ni++) {
            const int cl = wn * 32 + ni * 8 + (lane & 3) * 2;
            float b0 = 0.f, b1 = 0.f;
            if (bias) { b0 = bias[cl]; b1 = bias[cl + 1]; }
            float2 v0 = { d[mi][ni][0] + b0, d[mi][ni][1] + b1 };
            float2 v1 = { d[mi][ni][2] + b0, d[mi][ni][3] + b1 };
            *(float2*)(dst + (ull)r0 * ldc + coff + cl)       = v0;
            *(float2*)(dst + (ull)(r0 + 8) * ldc + coff + cl) = v1;
        }
    }
}

// ---------------- RoPE on Q -> Qh/Ql planes ----------------
__global__ void rope_q_kernel(const float* __restrict__ fcos, const float* __restrict__ fsin)
{
    const int t = blockIdx.x;
    const int h = threadIdx.x >> 6;
    const int i = threadIdx.x & 63;
    const float* q = g_q + (ull)t * HID + h * HD;
    const float c = fcos[t * 64 + i];
    const float s = fsin[t * 64 + i];
    const float x1 = q[i];
    const float x2 = q[i + 64];
    const float r1 = x1 * c - x2 * s;
    const float r2 = x1 * s + x2 * c;
    __nv_bfloat16 h1, l1, h2, l2;
    split2(r1, h1, l1); split2(r2, h2, l2);
    const ull base = ((ull)h * QL + t) * HD;
    g_qh[base + i] = h1;       g_qlo[base + i] = l1;
    g_qh[base + i + 64] = h2;  g_qlo[base + i + 64] = l2;
}

// ---------------- build full K planes + V (f32) ----------------
__global__ void build_kv_kernel(
    const float* __restrict__ k_hist, const float* __restrict__ v_hist,
    const float* __restrict__ fcos, const float* __restrict__ fsin)
{
    const int pos = blockIdx.x;
    const int kv = blockIdx.y;
    const int i = threadIdx.x;
    float* vd = g_v + ((ull)(kv * KLEN + pos)) * HD;
    float k1, k2;
    if (pos < HISTL) {
        const float* ks = k_hist + ((ull)pos * NKVH + kv) * HD;
        const float* vs = v_hist + ((ull)pos * NKVH + kv) * HD;
        k1 = ks[i]; k2 = ks[i + 64];
        vd[i] = vs[i]; vd[i + 64] = vs[i + 64];
    } else {
        const int t = pos - HISTL;
        const float* ks = g_kn + (ull)t * (NKVH * HD) + kv * HD;
        const float* vs = g_vn + (ull)t * (NKVH * HD) + kv * HD;
        const float c = fcos[t * 64 + i];
        const float s = fsin[t * 64 + i];
        const float x1 = ks[i];
        const float x2 = ks[i + 64];
        k1 = x1 * c - x2 * s;
        k2 = x1 * s + x2 * c;
        vd[i] = vs[i]; vd[i + 64] = vs[i + 64];
    }
    __nv_bfloat16 h1, l1, h2, l2;
    split2(k1, h1, l1); split2(k2, h2, l2);
    const ull base = ((ull)(kv * KLEN + pos)) * HD;
    g_kh[base + i] = h1;       g_klo[base + i] = l1;
    g_kh[base + i + 64] = h2;  g_klo[base + i + 64] = l2;
}

// ---------------- transpose V -> V^T planes ----------------
__global__ void vt_kernel() {
    __shared__ float t[32][33];
    const int pos0 = blockIdx.x * 32, d0 = blockIdx.y * 32, kv = blockIdx.z;
    const int tx = threadIdx.x, ty = threadIdx.y;
    for (int r = ty; r < 32; r += 8)
        t[r][tx] = g_v[((ull)(kv * KLEN + pos0 + r)) * HD + d0 + tx];
    __syncthreads();
    for (int r = ty; r < 32; r += 8) {
        __nv_bfloat16 h, l;
        split2(t[tx][r], h, l);
        const ull o = ((ull)(kv * HD + d0 + r)) * KLEN + pos0 + tx;
        g_vth[o] = h; g_vtl[o] = l;
    }
}

// ================= HMMA flash attention (plane-split, Q block-held) =================
#define QSTR 272            // Qh/Ql/Kh/Kl row stride (128 d x 2B + 16 pad)
#define VSTR 144            // Vh/Vl/Ph/Pl row stride (64 keys x 2B + 16 pad)
#define OFF_QH 0
#define OFF_QL 17408
#define OFF_KH 34816
#define OFF_KL 52224
#define OFF_V  69632        // per buf: Vh (18432) then Vl (18432); 2 bufs
#define VBUF_B 36864
#define OFF_PH 143360
#define OFF_PL 152576
#define OFF_RS 161792
#define ATT_SMEM 162816

__global__ __launch_bounds__(256, 1) void attention_kernel()
{
    extern __shared__ __align__(1024) char asmem[];
    const uint32_t sb = smem_u32(asmem);
    const int h  = blockIdx.x;
    const int qb = 31 - blockIdx.y;
    const int kvh = h / GRP;
    const int q0 = qb * 64;
    const int tid = threadIdx.x;
    const int lane = tid & 31;
    const int wid = tid >> 5;
    const int wm = wid >> 2;      // 0..1
    const int wn = wid & 3;       // 0..3
    const int n_tiles = qb + 33;

    const __nv_bfloat16* Qgh = g_qh  + ((ull)h * QL + q0) * HD;
    const __nv_bfloat16* Qgl = g_qlo + ((ull)h * QL + q0) * HD;
    const __nv_bfloat16* Kgh = g_kh  + ((ull)kvh * KLEN) * HD;
    const __nv_bfloat16* Kgl = g_klo + ((ull)kvh * KLEN) * HD;
    const __nv_bfloat16* Vgh = g_vth + ((ull)kvh * HD) * KLEN;
    const __nv_bfloat16* Vgl = g_vtl + ((ull)kvh * HD) * KLEN;

    // ---- prologue: Q planes + K[0] planes + V[0] planes ----
    for (int u = tid; u < 64 * 16; u += 256) {
        const int r = u >> 4, c = u & 15;
        cp_async16(sb + OFF_QH + r * QSTR + c * 16, Qgh + (ull)r * HD + c * 8);
        cp_async16(sb + OFF_QL + r * QSTR + c * 16, Qgl + (ull)r * HD + c * 8);
        cp_async16(sb + OFF_KH + r * QSTR + c * 16, Kgh + (ull)r * HD + c * 8);
        cp_async16(sb + OFF_KL + r * QSTR + c * 16, Kgl + (ull)r * HD + c * 8);
    }
    for (int u = tid; u < 128 * 8; u += 256) {
        const int r = u >> 3, c = u & 7;
        cp_async16(sb + OFF_V + r * VSTR + c * 16,         Vgh + (ull)r * KLEN + c * 8);
        cp_async16(sb + OFF_V + 18432 + r * VSTR + c * 16, Vgl + (ull)r * KLEN + c * 8);
    }
    cp_commit();

    float accO[2][4][4];
    float psum[2][2];
#pragma unroll
    for (int mi = 0; mi < 2; mi++) {
#pragma unroll
        for (int hf = 0; hf < 2; hf++) psum[mi][hf] = 0.f;
#pragma unroll
        for (int ni = 0; ni < 4; ni++)
#pragma unroll
            for (int r = 0; r < 4; r++) accO[mi][ni][r] = 0.f;
    }

    const int arow = wm * 32 + (lane & 15);
    const int acol = (lane & 16) ? 16 : 0;
    const int qbrow = wn * 16 + (lane & 7) + ((lane & 16) ? 8 : 0);
    const int vbrow = wn * 32 + (lane & 7) + ((lane & 16) ? 8 : 0);
    const int kbcol = (lane & 8) ? 16 : 0;

    // ---- load Qh fragments ONCE for the whole block (held in registers) ----
    cp_wait0();
    __syncthreads();
    uint32_t qfh[8][2][4];
#pragma unroll
    for (int kk = 0; kk < 8; kk++) {
        ldsm4(qfh[kk][0], sb + OFF_QH + (uint32_t)(arow * QSTR + kk * 32 + acol));
        ldsm4(qfh[kk][1], sb + OFF_QH + (uint32_t)((arow + 16) * QSTR + kk * 32 + acol));
    }

    for (int kt = 0; kt < n_tiles; kt++) {
        cp_wait0();
        __syncthreads();           // tile data ready; prev PV done

        // ==== S = Q K^T, 3 passes (Qh held in qfh across all tiles) ====
        float S[2][2][4];
#pragma unroll
        for (int mi = 0; mi < 2; mi++)
#pragma unroll
            for (int nf = 0; nf < 2; nf++)
#pragma unroll
                for (int r = 0; r < 4; r++) S[mi][nf][r] = 0.f;

        uint32_t kf[8][4];         // Kh fragments, held within tile
        // pass 1: Qh * Kh  (K load + hold)
#pragma unroll
        for (int kk = 0; kk < 8; kk++) {
            ldsm4(kf[kk], sb + OFF_KH + (uint32_t)(qbrow * QSTR + kk * 32 + kbcol));
            mma16816(S[0][0], qfh[kk][0], &kf[kk][0]);
            mma16816(S[0][1], qfh[kk][0], &kf[kk][2]);
            mma16816(S[1][0], qfh[kk][1], &kf[kk][0]);
            mma16816(S[1][1], qfh[kk][1], &kf[kk][2]);
        }
        // pass 2: Qh * Kl  (Kl streamed)
#pragma unroll
        for (int kk = 0; kk < 8; kk++) {
            uint32_t t4[4];
            ldsm4(t4, sb + OFF_KL + (uint32_t)(qbrow * QSTR + kk * 32 + kbcol));
            mma16816(S[0][0], qfh[kk][0], &t4[0]);
            mma16816(S[0][1], qfh[kk][0], &t4[2]);
            mma16816(S[1][0], qfh[kk][1], &t4[0]);
            mma16816(S[1][1], qfh[kk][1], &t4[2]);
        }
        // pass 3: Ql * Kh  (Ql streamed, Kh held)
#pragma unroll
        for (int kk = 0; kk < 8; kk++) {
            uint32_t t0[4], t1[4];
            ldsm4(t0, sb + OFF_QL + (uint32_t)(arow * QSTR + kk * 32 + acol));
            ldsm4(t1, sb + OFF_QL + (uint32_t)((arow + 16) * QSTR + kk * 32 + acol));
            mma16816(S[0][0], t0, &kf[kk][0]);
            mma16816(S[0][1], t0, &kf[kk][2]);
            mma16816(S[1][0], t1, &kf[kk][0]);
            mma16816(S[1][1], t1, &kf[kk][2]);
        }
        __syncthreads();           // all QK ldsm done -> K SMEM reusable

        // ---- prefetch next tile's K planes (+V alt buffer planes) ----
        if (kt + 1 < n_tiles) {
            const int kb2 = (kt + 1) * 64;
            for (int u = tid; u < 64 * 16; u += 256) {
                const int r = u >> 4, c = u & 15;
                cp_async16(sb + OFF_KH + r * QSTR + c * 16, Kgh + (ull)(kb2 + r) * HD + c * 8);
                cp_async16(sb + OFF_KL + r * QSTR + c * 16, Kgl + (ull)(kb2 + r) * HD + c * 8);
            }
            const uint32_t vbuf = sb + OFF_V + ((kt + 1) & 1) * VBUF_B;
            for (int u = tid; u < 128 * 8; u += 256) {
                const int r = u >> 3, c = u & 7;
                cp_async16(vbuf + r * VSTR + c * 16,         Vgh + (ull)r * KLEN + kb2 + c * 8);
                cp_async16(vbuf + 18432 + r * VSTR + c * 16, Vgl + (ull)r * KLEN + kb2 + c * 8);
            }
            cp_commit();
        }

        // ---- scale + mask + exp + write Ph/Pl planes + partial sums ----
        const int kb = kt * 64;
        const bool maskt = (kt == qb + 32);
#pragma unroll
        for (int mi = 0; mi < 2; mi++)
#pragma unroll
            for (int nf = 0; nf < 2; nf++)
#pragma unroll
                for (int hf = 0; hf < 2; hf++) {
                    float s0 = S[mi][nf][hf * 2 + 0] * 0.08838834764831845f;
                    float s1 = S[mi][nf][hf * 2 + 1] * 0.08838834764831845f;
                    if (maskt) {
                        const int qg = q0 + wm * 32 + mi * 16 + (lane >> 2) + hf * 8;
                        const int kg = kb + wn * 16 + nf * 8 + (lane & 3) * 2;
                        if (kg > qg + HISTL)     s0 = -1e30f;
                        if (kg + 1 > qg + HISTL) s1 = -1e30f;
                    }
                    const float p0 = __expf(s0);
                    const float p1 = __expf(s1);
                    psum[mi][hf] += p0 + p1;
                    __nv_bfloat16 h0, l0, h1, l1;
                    split2(p0, h0, l0); split2(p1, h1, l1);
                    const int row = wm * 32 + mi * 16 + hf * 8 + (lane >> 2);
                    const int c2 = wn * 16 + nf * 8 + (lane & 3) * 2;
                    *(uint32_t*)(asmem + OFF_PH + row * VSTR + 2 * c2) = bfpack(h0, h1);
                    *(uint32_t*)(asmem + OFF_PL + row * VSTR + 2 * c2) = bfpack(l0, l1);
                }
        __syncthreads();           // P planes ready

        // ==== O += P @ V^T, 3 passes with held fragments ====
        const uint32_t sPH = sb + OFF_PH;
        const uint32_t sPL = sb + OFF_PL;
        const uint32_t sVH = sb + OFF_V + (kt & 1) * VBUF_B;
        const uint32_t sVL = sVH + 18432;

        uint32_t pf[4][2][4];      // Ph fragments, held
        uint32_t vf[4][2][4];      // Vh fragments, held
        // pass 1: Ph * Vh
#pragma unroll
        for (int kk = 0; kk < 4; kk++) {
            ldsm4(pf[kk][0], sPH + (uint32_t)(arow * VSTR + kk * 32 + acol));
            ldsm4(pf[kk][1], sPH + (uint32_t)((arow + 16) * VSTR + kk * 32 + acol));
            ldsm4(vf[kk][0], sVH + (uint32_t)(vbrow * VSTR + kk * 32 + kbcol));
            ldsm4(vf[kk][1], sVH + (uint32_t)((vbrow + 16) * VSTR + kk * 32 + kbcol));
            mma16816(accO[0][0], pf[kk][0], &vf[kk][0][0]);
            mma16816(accO[0][1], pf[kk][0], &vf[kk][0][2]);
            mma16816(accO[0][2], pf[kk][0], &vf[kk][1][0]);
            mma16816(accO[0][3], pf[kk][0], &vf[kk][1][2]);
            mma16816(accO[1][0], pf[kk][1], &vf[kk][0][0]);
            mma16816(accO[1][1], pf[kk][1], &vf[kk][0][2]);
            mma16816(accO[1][2], pf[kk][1], &vf[kk][1][0]);
            mma16816(accO[1][3], pf[kk][1], &vf[kk][1][2]);
        }
        // pass 2: Ph * Vl  (Ph held, Vl streamed)
#pragma unroll
        for (int kk = 0; kk < 4; kk++) {
            uint32_t t0[4], t1[4];
            ldsm4(t0, sVL + (uint32_t)(vbrow * VSTR + kk * 32 + kbcol));
            ldsm4(t1, sVL + (uint32_t)((vbrow + 16) * VSTR + kk * 32 + kbcol));
            mma16816(accO[0][0], pf[kk][0], &t0[0]);
            mma16816(accO[0][1], pf[kk][0], &t0[2]);
            mma16816(accO[0][2], pf[kk][0], &t1[0]);
            mma16816(accO[0][3], pf[kk][0], &t1[2]);
            mma16816(accO[1][0], pf[kk][1], &t0[0]);
            mma16816(accO[1][1], pf[kk][1], &t0[2]);
            mma16816(accO[1][2], pf[kk][1], &t1[0]);
            mma16816(accO[1][3], pf[kk][1], &t1[2]);
        }
        // pass 3: Pl * Vh  (Pl streamed, Vh held)
#pragma unroll
        for (int kk = 0; kk < 4; kk++) {
            uint32_t p0[4], p1[4];
            ldsm4(p0, sPL + (uint32_t)(arow * VSTR + kk * 32 + acol));
            ldsm4(p1, sPL + (uint32_t)((arow + 16) * VSTR + kk * 32 + acol));
            mma16816(accO[0][0], p0, &vf[kk][0][0]);
            mma16816(accO[0][1], p0, &vf[kk][0][2]);
            mma16816(accO[0][2], p0, &vf[kk][1][0]);
            mma16816(accO[0][3], p0, &vf[kk][1][2]);
            mma16816(accO[1][0], p1, &vf[kk][0][0]);
            mma16816(accO[1][1], p1, &vf[kk][0][2]);
            mma16816(accO[1][2], p1, &vf[kk][1][0]);
            mma16816(accO[1][3], p1, &vf[kk][1][2]);
        }
    }

    // ---- one-time row-sum reduction ----
    float* rs = (float*)(asmem + OFF_RS);
#pragma unroll
    for (int mi = 0; mi < 2; mi++)
#pragma unroll
        for (int hf = 0; hf < 2; hf++) {
            float v = psum[mi][hf];
            v += __shfl_xor_sync(0xffffffffu, v, 1);
            v += __shfl_xor_sync(0xffffffffu, v, 2);
            psum[mi][hf] = v;
        }
    __syncthreads();
    if ((lane & 3) == 0) {
#pragma unroll
        for (int mi = 0; mi < 2; mi++)
#pragma unroll
            for (int hf = 0; hf < 2; hf++)
                rs[wn * 64 + wm * 32 + mi * 16 + hf * 8 + (lane >> 2)] = psum[mi][hf];
    }
    __syncthreads();

    // ---- epilogue: normalize, write g_at3 triplets (A-side h,h,l) ----
#pragma unroll
    for (int mi = 0; mi < 2; mi++) {
#pragma unroll
        for (int hf = 0; hf < 2; hf++) {
            const int lrow = wm * 32 + mi * 16 + hf * 8 + (lane >> 2);
            const float lsum = rs[0 * 64 + lrow] + rs[1 * 64 + lrow]
                             + rs[2 * 64 + lrow] + rs[3 * 64 + lrow];
            const float inv = 1.f / lsum;
            const int row = q0 + lrow;
#pragma unroll
            for (int ni = 0; ni < 4; ni++) {
                const int dcol = wn * 32 + ni * 8 + (lane & 3) * 2;
                const float v0 = accO[mi][ni][hf * 2 + 0] * inv;
                const float v1 = accO[mi][ni][hf * 2 + 1] * inv;
                __nv_bfloat16 h0, l0, h1, l1;
                split2(v0, h0, l0); split2(v1, h1, l1);
                uint32_t* dp = (uint32_t*)(g_at3 + (ull)row * K3 + 3 * (h * HD + dcol));
                dp[0] = bfpack(h0, h0);
                dp[1] = bfpack(l0, h1);
                dp[2] = bfpack(h1, l1);
            }
        }
    }
}

// ---------------- launch ----------------
extern "C" void kernel_launch(void* const* d_in, const int* in_sizes, int n_in,
                              void* d_out, int out_size)
{
    const float* x     = (const float*)d_in[0];
    const float* Wq    = (const float*)d_in[1];
    const float* bq    = (const float*)d_in[2];
    const float* Wk    = (const float*)d_in[3];
    const float* bk    = (const float*)d_in[4];
    const float* Wv    = (const float*)d_in[5];
    const float* bv    = (const float*)d_in[6];
    const float* Wo    = (const float*)d_in[7];
    const float* khist = (const float*)d_in[8];
    const float* vhist = (const float*)d_in[9];
    const float* fcos  = (const float*)d_in[10];
    const float* fsin  = (const float*)d_in[11];
    float* out = (float*)d_out;

    cudaFuncSetAttribute(attention_kernel,
                         cudaFuncAttributeMaxDynamicSharedMemorySize, ATT_SMEM);
    cudaFuncSetAttribute(hmma_gemm_kernel,
                         cudaFuncAttributeMaxDynamicSharedMemorySize, GEMM_SMEM);

    conv_x3_kernel<<<QL * HID / 256, 256>>>(x);
    conv_wqkv3_kernel<<<dim3(64, 48), dim3(32, 8)>>>(Wq, Wk, Wv);
    conv_wo3_kernel<<<dim3(48, 48), dim3(32, 8)>>>(Wo);

    hmma_gemm_kernel<<<dim3(16, 16), 256, GEMM_SMEM>>>(0, nullptr, bq, bk, bv);

    rope_q_kernel<<<QL, NH * 64>>>(fcos, fsin);
    build_kv_kernel<<<dim3(KLEN, NKVH), 64>>>(khist, vhist, fcos, fsin);
    vt_kernel<<<dim3(KLEN / 32, HD / 32, NKVH), dim3(32, 8)>>>();

    attention_kernel<<<dim3(NH, 32), 256, ATT_SMEM>>>();

    hmma_gemm_kernel<<<dim3(12, 16), 256, GEMM_SMEM>>>(1, out, nullptr, nullptr, nullptr);
}